// round 2
// baseline (speedup 1.0000x reference)
#include <cuda_runtime.h>
#include <math.h>

#define N_NODES 100000
#define N_EDGES 3200000
#define DIMC 32
#define INDIM 128
#define NGRAPH 250
#define NPER 400
#define KTOP 100
#define TOTALC 97

// ---------------- device scratch (no allocations allowed) ----------------
__device__ float g_deg[N_NODES];
__device__ float g_dis[N_NODES];
__device__ float g_deginv[N_NODES];
__device__ float g_coef[N_EDGES];
__device__ float g_h[N_NODES * DIMC];
__device__ float g_agg[N_NODES * DIMC];
__device__ float g_x1[N_NODES * DIMC];
__device__ float g_x2[N_NODES * DIMC];
__device__ float g_x3[N_NODES * DIMC];
__device__ float g_h4[N_NODES];
__device__ float g_agg4[N_NODES];
__device__ float g_score[N_NODES];
__device__ int   g_topk[NGRAPH * KTOP];
__device__ float g_p1[NGRAPH * 128 * 50];
__device__ float g_c2f[NGRAPH * 2944];
__device__ float g_hfc[NGRAPH * 128];

// ---------------- degree / normalization ----------------
__global__ void k_deg_init() {
    int i = blockIdx.x * 256 + threadIdx.x;
    if (i < N_NODES) g_deg[i] = 1.0f;   // +1 self loop
}
__global__ void k_deg_acc(const int* __restrict__ dst) {
    int e = blockIdx.x * 256 + threadIdx.x;
    if (e < N_EDGES) atomicAdd(&g_deg[dst[e]], 1.0f);
}
__global__ void k_deg_fin() {
    int i = blockIdx.x * 256 + threadIdx.x;
    if (i < N_NODES) {
        float d = g_deg[i];
        g_dis[i] = rsqrtf(d);
        g_deginv[i] = 1.0f / d;
    }
}
__global__ void k_coef(const int* __restrict__ src, const int* __restrict__ dst) {
    int e = blockIdx.x * 256 + threadIdx.x;
    if (e < N_EDGES) g_coef[e] = g_dis[src[e]] * g_dis[dst[e]];
}

// ---------------- h = X @ W  (also zeroes agg) ----------------
// blockDim 256 = 8 nodes x 32 output dims; W staged in shared.
__global__ void k_gemm(const float* __restrict__ Xext, int xsel, int Kdim,
                       const float* __restrict__ W) {
    __shared__ float Ws[INDIM * DIMC];
    const float* X = (xsel == 0) ? Xext : (xsel == 1 ? g_x1 : g_x2);
    int tid = threadIdx.x;
    for (int i = tid; i < Kdim * DIMC; i += 256) Ws[i] = W[i];
    __syncthreads();
    int node = blockIdx.x * 8 + (tid >> 5);
    if (node >= N_NODES) return;
    int dim = tid & 31;
    const float* xr = X + (size_t)node * Kdim;
    float acc = 0.0f;
#pragma unroll 4
    for (int k = 0; k < Kdim; k++) acc = fmaf(xr[k], Ws[k * DIMC + dim], acc);
    g_h[node * DIMC + dim] = acc;
    g_agg[node * DIMC + dim] = 0.0f;
}

// ---------------- edge scatter: agg[dst] += coef * h[src] ----------------
// 8 consecutive threads per edge (4 dims each via float4 + red.v4).
__global__ void k_scatter(const int* __restrict__ src, const int* __restrict__ dst) {
    unsigned tid = blockIdx.x * 256u + threadIdx.x;
    unsigned e = tid >> 3;
    if (e >= N_EDGES) return;
    int part = tid & 7;
    int s = src[e], d = dst[e];
    float c = g_coef[e];
    const float4 v = *reinterpret_cast<const float4*>(&g_h[s * DIMC + part * 4]);
    float* p = &g_agg[d * DIMC + part * 4];
    asm volatile("red.global.add.v4.f32 [%0], {%1,%2,%3,%4};"
                 :: "l"(p), "f"(v.x * c), "f"(v.y * c), "f"(v.z * c), "f"(v.w * c)
                 : "memory");
}

// ---------------- out = tanh(agg + h*deginv + b) ----------------
__global__ void k_combine(const float* __restrict__ b, int osel) {
    int i = blockIdx.x * 256 + threadIdx.x;
    if (i >= N_NODES * DIMC) return;
    int n = i >> 5, d = i & 31;
    float v = tanhf(g_agg[i] + g_h[i] * g_deginv[n] + b[d]);
    float* O = (osel == 1) ? g_x1 : (osel == 2 ? g_x2 : g_x3);
    O[i] = v;
}

// ---------------- layer 4 (dim 1) ----------------
__global__ void k_gemm4(const float* __restrict__ W4) {
    int n = blockIdx.x * 256 + threadIdx.x;
    if (n >= N_NODES) return;
    float acc = 0.0f;
#pragma unroll
    for (int k = 0; k < DIMC; k++) acc = fmaf(g_x2[n * DIMC + k], W4[k], acc);
    g_h4[n] = acc;
    g_agg4[n] = 0.0f;
}
__global__ void k_scatter4(const int* __restrict__ src, const int* __restrict__ dst) {
    int e = blockIdx.x * 256 + threadIdx.x;
    if (e >= N_EDGES) return;
    atomicAdd(&g_agg4[dst[e]], g_h4[src[e]] * g_coef[e]);
}
__global__ void k_combine4(const float* __restrict__ b4) {
    int n = blockIdx.x * 256 + threadIdx.x;
    if (n >= N_NODES) return;
    g_score[n] = tanhf(g_agg4[n] + g_h4[n] * g_deginv[n] + b4[0]);
}

// ---------------- sort pooling: per-graph bitonic-512, top-100 ----------------
// Key: score descending, tie -> node index ascending (matches stable lexsort).
__global__ void k_sortpool() {
    __shared__ float s[512];
    __shared__ int   si[512];
    int g = blockIdx.x, tid = threadIdx.x;  // 256 threads
    for (int i = tid; i < 512; i += 256) {
        if (i < NPER) { s[i] = g_score[g * NPER + i]; si[i] = i; }
        else          { s[i] = __int_as_float(0xff800000); si[i] = 0x7FFFFFFF; }
    }
    __syncthreads();
    for (int k = 2; k <= 512; k <<= 1) {
        for (int j = k >> 1; j > 0; j >>= 1) {
            for (int i = tid; i < 512; i += 256) {
                int ixj = i ^ j;
                if (ixj > i) {
                    float a = s[i], b = s[ixj];
                    int ia = si[i], ib = si[ixj];
                    bool before = (a > b) || (a == b && ia < ib);
                    bool dirDesc = ((i & k) == 0);
                    if (dirDesc ? !before : before) {
                        s[i] = b; s[ixj] = a; si[i] = ib; si[ixj] = ia;
                    }
                }
            }
            __syncthreads();
        }
    }
    if (tid < KTOP) g_topk[g * KTOP + tid] = g * NPER + si[tid];
}

// ---------------- conv1 (per-slot linear) + relu + maxpool(2,2) ----------------
__global__ void k_conv1pool(const float* __restrict__ cw1, const float* __restrict__ cb1) {
    __shared__ float xs[KTOP * TOTALC];  // 100 x 97 = 38.8 KB
    int g = blockIdx.x, tid = threadIdx.x;  // 256 threads
    for (int i = tid; i < KTOP * TOTALC; i += 256) {
        int kslot = i / TOTALC, t = i - kslot * TOTALC;
        int n = g_topk[g * KTOP + kslot];
        float v;
        if (t < 32)      v = g_x1[n * DIMC + t];
        else if (t < 64) v = g_x2[n * DIMC + t - 32];
        else if (t < 96) v = g_x3[n * DIMC + t - 64];
        else             v = g_score[n];
        xs[i] = v;
    }
    __syncthreads();
    for (int out = tid; out < 128 * 50; out += 256) {
        int c = out / 50, j = out - c * 50;
        const float* w = cw1 + c * TOTALC;
        const float* r0 = xs + (2 * j) * TOTALC;
        const float* r1 = xs + (2 * j + 1) * TOTALC;
        float a0 = cb1[c], a1 = a0;
#pragma unroll 4
        for (int t = 0; t < TOTALC; t++) {
            float wv = w[t];
            a0 = fmaf(r0[t], wv, a0);
            a1 = fmaf(r1[t], wv, a1);
        }
        g_p1[(g * 128 + c) * 50 + j] = fmaxf(fmaxf(a0, a1), 0.0f);
    }
}

// ---------------- conv2 (128->64, k=5) + relu ----------------
__global__ void k_conv2(const float* __restrict__ cw2, const float* __restrict__ cb2) {
    __shared__ float ps[128 * 50];  // 25.6 KB
    int g = blockIdx.x, tid = threadIdx.x;  // 256 threads
    for (int i = tid; i < 128 * 50; i += 256) ps[i] = g_p1[g * 6400 + i];
    __syncthreads();
    for (int out = tid; out < 64 * 46; out += 256) {
        int o = out / 46, j = out - o * 46;
        const float* w = cw2 + o * 640;  // [o][i][h]
        float acc = cb2[o];
#pragma unroll 4
        for (int i = 0; i < 128; i++) {
            const float* pr = ps + i * 50 + j;
            const float* wr = w + i * 5;
            acc = fmaf(pr[0], wr[0], acc);
            acc = fmaf(pr[1], wr[1], acc);
            acc = fmaf(pr[2], wr[2], acc);
            acc = fmaf(pr[3], wr[3], acc);
            acc = fmaf(pr[4], wr[4], acc);
        }
        g_c2f[g * 2944 + o * 46 + j] = fmaxf(acc, 0.0f);
    }
}

// ---------------- fc1 + relu (4 graphs per block to amortize fw1 reads) ----------------
__global__ void k_fc1(const float* __restrict__ fw1, const float* __restrict__ fb1) {
    __shared__ float cs[4 * 2944];  // 47.1 KB
    int gb = blockIdx.x, tid = threadIdx.x;  // 128 threads
    int g0 = gb * 4;
    for (int i = tid; i < 4 * 2944; i += 128) {
        int g = g0 + i / 2944;
        cs[i] = (g < NGRAPH) ? g_c2f[g * 2944 + (i % 2944)] : 0.0f;
    }
    __syncthreads();
    const float4* wr = reinterpret_cast<const float4*>(fw1 + (size_t)tid * 2944);
    const float4* c0 = reinterpret_cast<const float4*>(cs);
    const float4* c1 = reinterpret_cast<const float4*>(cs + 2944);
    const float4* c2 = reinterpret_cast<const float4*>(cs + 2 * 2944);
    const float4* c3 = reinterpret_cast<const float4*>(cs + 3 * 2944);
    float a0 = 0, a1 = 0, a2 = 0, a3 = 0;
    for (int d = 0; d < 736; d++) {
        float4 w = wr[d];
        float4 v;
        v = c0[d]; a0 += w.x * v.x + w.y * v.y + w.z * v.z + w.w * v.w;
        v = c1[d]; a1 += w.x * v.x + w.y * v.y + w.z * v.z + w.w * v.w;
        v = c2[d]; a2 += w.x * v.x + w.y * v.y + w.z * v.z + w.w * v.w;
        v = c3[d]; a3 += w.x * v.x + w.y * v.y + w.z * v.z + w.w * v.w;
    }
    float bb = fb1[tid];
    if (g0 + 0 < NGRAPH) g_hfc[(g0 + 0) * 128 + tid] = fmaxf(a0 + bb, 0.0f);
    if (g0 + 1 < NGRAPH) g_hfc[(g0 + 1) * 128 + tid] = fmaxf(a1 + bb, 0.0f);
    if (g0 + 2 < NGRAPH) g_hfc[(g0 + 2) * 128 + tid] = fmaxf(a2 + bb, 0.0f);
    if (g0 + 3 < NGRAPH) g_hfc[(g0 + 3) * 128 + tid] = fmaxf(a3 + bb, 0.0f);
}

// ---------------- fc3 + log_softmax ----------------
__global__ void k_fc3(const float* __restrict__ fw3, const float* __restrict__ fb3,
                      float* __restrict__ out) {
    int b = blockIdx.x * 256 + threadIdx.x;
    if (b >= NGRAPH) return;
    float l0 = fb3[0], l1 = fb3[1];
#pragma unroll 4
    for (int d = 0; d < 128; d++) {
        float h = g_hfc[b * 128 + d];
        l0 = fmaf(h, fw3[d], l0);
        l1 = fmaf(h, fw3[128 + d], l1);
    }
    float m = fmaxf(l0, l1);
    float lse = m + logf(expf(l0 - m) + expf(l1 - m));
    out[b * 2 + 0] = l0 - lse;
    out[b * 2 + 1] = l1 - lse;
}

// ---------------- launch ----------------
extern "C" void kernel_launch(void* const* d_in, const int* in_sizes, int n_in,
                              void* d_out, int out_size) {
    const float* x   = (const float*)d_in[0];
    const int*   ei  = (const int*)d_in[1];
    const int*   src = ei;
    const int*   dst = ei + N_EDGES;
    const float* W1 = (const float*)d_in[3];  const float* b1 = (const float*)d_in[4];
    const float* W2 = (const float*)d_in[5];  const float* b2 = (const float*)d_in[6];
    const float* W3 = (const float*)d_in[7];  const float* b3 = (const float*)d_in[8];
    const float* W4 = (const float*)d_in[9];  const float* b4 = (const float*)d_in[10];
    const float* cw1 = (const float*)d_in[11]; const float* cb1 = (const float*)d_in[12];
    const float* cw2 = (const float*)d_in[13]; const float* cb2 = (const float*)d_in[14];
    const float* fw1 = (const float*)d_in[15]; const float* fb1 = (const float*)d_in[16];
    const float* fw3 = (const float*)d_in[17]; const float* fb3 = (const float*)d_in[18];
    float* out = (float*)d_out;

    const int TB = 256;
    const int gN  = (N_NODES + TB - 1) / TB;          // 391
    const int gE  = (N_EDGES + TB - 1) / TB;          // 12500
    const int gNE = (N_EDGES * 8 + TB - 1) / TB;      // 100000
    const int gND = (N_NODES * DIMC + TB - 1) / TB;   // 12500
    const int gG8 = (N_NODES + 7) / 8;                // 12500

    k_deg_init<<<gN, TB>>>();
    k_deg_acc<<<gE, TB>>>(dst);
    k_deg_fin<<<gN, TB>>>();
    k_coef<<<gE, TB>>>(src, dst);

    // layer 1: x (128) -> x1
    k_gemm<<<gG8, TB>>>(x, 0, INDIM, W1);
    k_scatter<<<gNE, TB>>>(src, dst);
    k_combine<<<gND, TB>>>(b1, 1);
    // layer 2: x1 -> x2
    k_gemm<<<gG8, TB>>>(nullptr, 1, DIMC, W2);
    k_scatter<<<gNE, TB>>>(src, dst);
    k_combine<<<gND, TB>>>(b2, 2);
    // layer 3: x2 -> x3
    k_gemm<<<gG8, TB>>>(nullptr, 2, DIMC, W3);
    k_scatter<<<gNE, TB>>>(src, dst);
    k_combine<<<gND, TB>>>(b3, 3);
    // layer 4: x2 -> score (dim 1)
    k_gemm4<<<gN, TB>>>(W4);
    k_scatter4<<<gE, TB>>>(src, dst);
    k_combine4<<<gN, TB>>>(b4);

    k_sortpool<<<NGRAPH, TB>>>();
    k_conv1pool<<<NGRAPH, TB>>>(cw1, cb1);
    k_conv2<<<NGRAPH, TB>>>(cw2, cb2);
    k_fc1<<<(NGRAPH + 3) / 4, 128>>>(fw1, fb1);
    k_fc3<<<1, TB>>>(fw3, fb3, out);
}

// round 3
// speedup vs baseline: 1.1043x; 1.1043x over previous
#include <cuda_runtime.h>
#include <math.h>

#define N_NODES 100000
#define N_EDGES 3200000
#define DIMC 32
#define INDIM 128
#define NGRAPH 250
#define NPER 400
#define KTOP 100
#define TOTALC 97
#define SCAN_BLK 1024
#define NBLK_SCAN ((N_NODES + SCAN_BLK - 1) / SCAN_BLK)   // 98

// ---------------- device scratch ----------------
__device__ int   g_cnt[N_NODES];
__device__ int   g_fill[N_NODES];
__device__ int   g_off[N_NODES + 1];
__device__ int   g_bsum[NBLK_SCAN];
__device__ float g_dis[N_NODES];
__device__ float g_deginv[N_NODES];
__device__ int2  g_csr[N_EDGES];          // {src, coef bits}
__device__ float g_h[N_NODES * DIMC];
__device__ float g_z[N_NODES * DIMC];
__device__ float g_x1[N_NODES * DIMC];
__device__ float g_x2[N_NODES * DIMC];
__device__ float g_x3[N_NODES * DIMC];
__device__ float g_score[N_NODES];
__device__ int   g_topk[NGRAPH * KTOP];
__device__ float g_p1[NGRAPH * 128 * 50];
__device__ float g_c2f[NGRAPH * 2944];
__device__ float g_hfc[NGRAPH * 128];

// ---------------- CSR build ----------------
__global__ void k_hist_init() {
    int i = blockIdx.x * 256 + threadIdx.x;
    if (i < N_NODES) g_cnt[i] = 0;
}
__global__ void k_hist(const int* __restrict__ dst) {
    int e = blockIdx.x * 256 + threadIdx.x;
    if (e < N_EDGES) atomicAdd(&g_cnt[dst[e]], 1);
}
// block-level exclusive scan of counts (Hillis-Steele in shared)
__global__ void k_scanA() {
    __shared__ int s[SCAN_BLK];
    int tid = threadIdx.x;
    int i = blockIdx.x * SCAN_BLK + tid;
    int v = (i < N_NODES) ? g_cnt[i] : 0;
    s[tid] = v;
    __syncthreads();
    for (int o = 1; o < SCAN_BLK; o <<= 1) {
        int t = (tid >= o) ? s[tid - o] : 0;
        __syncthreads();
        s[tid] += t;
        __syncthreads();
    }
    if (i < N_NODES) g_off[i] = s[tid] - v;   // exclusive within block
    if (tid == SCAN_BLK - 1) g_bsum[blockIdx.x] = s[tid];
}
__global__ void k_scanB() {
    __shared__ int bs[NBLK_SCAN];
    int tid = threadIdx.x;
    if (tid < NBLK_SCAN) bs[tid] = g_bsum[tid];
    __syncthreads();
    if (tid == 0) {
        int run = 0;
        for (int b = 0; b < NBLK_SCAN; b++) { int t = bs[b]; bs[b] = run; run += t; }
        g_off[N_NODES] = N_EDGES;
    }
    __syncthreads();
    if (tid < NBLK_SCAN) g_bsum[tid] = bs[tid];
}
__global__ void k_scanC() {
    int i = blockIdx.x * 256 + threadIdx.x;
    if (i >= N_NODES) return;
    g_off[i] += g_bsum[i / SCAN_BLK];
    g_fill[i] = 0;
    float d = (float)g_cnt[i] + 1.0f;
    g_dis[i] = rsqrtf(d);
    g_deginv[i] = 1.0f / d;
}
__global__ void k_fill(const int* __restrict__ src, const int* __restrict__ dst) {
    int e = blockIdx.x * 256 + threadIdx.x;
    if (e >= N_EDGES) return;
    int s = src[e], d = dst[e];
    int pos = g_off[d] + atomicAdd(&g_fill[d], 1);
    float c = g_dis[s] * g_dis[d];
    g_csr[pos] = make_int2(s, __float_as_int(c));
}

// ---------------- h = X @ W1 (128 -> 32) ----------------
__global__ void k_gemm1(const float* __restrict__ X, const float* __restrict__ W) {
    __shared__ float Ws[INDIM * DIMC];
    int tid = threadIdx.x;
    for (int i = tid; i < INDIM * DIMC; i += 256) Ws[i] = W[i];
    __syncthreads();
    int node = blockIdx.x * 8 + (tid >> 5);
    if (node >= N_NODES) return;
    int dim = tid & 31;
    const float* xr = X + (size_t)node * INDIM;
    float acc = 0.0f;
#pragma unroll 8
    for (int k = 0; k < INDIM; k++) acc = fmaf(xr[k], Ws[k * DIMC + dim], acc);
    g_h[node * DIMC + dim] = acc;
}

// ---------------- CSR gather: z = A*X + deginv*X ----------------
// warp per node; shfl-broadcast edge batches; fully coalesced 128B row reads.
// outsel==1: x1 = tanh(z + b)   (layer 1, X = g_h)
// outsel==0: g_z = z            (raw aggregate for layers 2 / 3+4)
__global__ void k_gather(int insel, int outsel, const float* __restrict__ bias) {
    const float* __restrict__ X = (insel == 0) ? g_h : (insel == 1 ? g_x1 : g_x2);
    int node = blockIdx.x * 8 + (threadIdx.x >> 5);
    if (node >= N_NODES) return;
    int lane = threadIdx.x & 31;
    int beg = g_off[node], end = g_off[node + 1];
    float acc = 0.0f;
    for (int base = beg; base < end; base += 32) {
        int idx = base + lane;
        int2 ec = (idx < end) ? g_csr[idx] : make_int2(0, 0);
        int m = min(32, end - base);
#pragma unroll 4
        for (int j = 0; j < m; j++) {
            int ss = __shfl_sync(0xffffffffu, ec.x, j);
            float cc = __shfl_sync(0xffffffffu, __int_as_float(ec.y), j);
            acc = fmaf(cc, X[ss * DIMC + lane], acc);
        }
    }
    float v = acc + X[node * DIMC + lane] * g_deginv[node];
    if (outsel == 1) g_x1[node * DIMC + lane] = tanhf(v + bias[lane]);
    else             g_z[node * DIMC + lane] = v;
}

// ---------------- out = tanh(z@W + b); layer 3 also emits score = tanh(z.W4+b4) ----------------
__global__ void k_zgemm(int layer, const float* __restrict__ W, const float* __restrict__ b,
                        const float* __restrict__ W4, const float* __restrict__ b4) {
    __shared__ float Ws[DIMC * DIMC];
    int tid = threadIdx.x;
    for (int i = tid; i < DIMC * DIMC; i += 256) Ws[i] = W[i];
    __syncthreads();
    int node = blockIdx.x * 8 + (tid >> 5);
    if (node >= N_NODES) return;
    int lane = tid & 31;
    float zk = g_z[node * DIMC + lane];
    float acc = 0.0f;
#pragma unroll
    for (int j = 0; j < DIMC; j++) {
        float zz = __shfl_sync(0xffffffffu, zk, j);
        acc = fmaf(zz, Ws[j * DIMC + lane], acc);
    }
    float o = tanhf(acc + b[lane]);
    if (layer == 2) g_x2[node * DIMC + lane] = o;
    else {
        g_x3[node * DIMC + lane] = o;
        float t = zk * W4[lane];
#pragma unroll
        for (int off = 16; off; off >>= 1) t += __shfl_xor_sync(0xffffffffu, t, off);
        if (lane == 0) g_score[node] = tanhf(t + b4[0]);
    }
}

// ---------------- sort pooling: per-graph bitonic-512, top-100 ----------------
__global__ void k_sortpool() {
    __shared__ float s[512];
    __shared__ int   si[512];
    int g = blockIdx.x, tid = threadIdx.x;  // 256 threads
    for (int i = tid; i < 512; i += 256) {
        if (i < NPER) { s[i] = g_score[g * NPER + i]; si[i] = i; }
        else          { s[i] = __int_as_float(0xff800000); si[i] = 0x7FFFFFFF; }
    }
    __syncthreads();
    for (int k = 2; k <= 512; k <<= 1) {
        for (int j = k >> 1; j > 0; j >>= 1) {
            for (int i = tid; i < 512; i += 256) {
                int ixj = i ^ j;
                if (ixj > i) {
                    float a = s[i], bb = s[ixj];
                    int ia = si[i], ib = si[ixj];
                    bool before = (a > bb) || (a == bb && ia < ib);
                    bool dirDesc = ((i & k) == 0);
                    if (dirDesc ? !before : before) {
                        s[i] = bb; s[ixj] = a; si[i] = ib; si[ixj] = ia;
                    }
                }
            }
            __syncthreads();
        }
    }
    if (tid < KTOP) g_topk[g * KTOP + tid] = g * NPER + si[tid];
}

// ---------------- conv1 (per-slot linear) + relu + maxpool(2,2) ----------------
__global__ void k_conv1pool(const float* __restrict__ cw1, const float* __restrict__ cb1) {
    __shared__ float xs[KTOP * TOTALC];
    int g = blockIdx.x, tid = threadIdx.x;  // 256 threads
    for (int i = tid; i < KTOP * TOTALC; i += 256) {
        int kslot = i / TOTALC, t = i - kslot * TOTALC;
        int n = g_topk[g * KTOP + kslot];
        float v;
        if (t < 32)      v = g_x1[n * DIMC + t];
        else if (t < 64) v = g_x2[n * DIMC + t - 32];
        else if (t < 96) v = g_x3[n * DIMC + t - 64];
        else             v = g_score[n];
        xs[i] = v;
    }
    __syncthreads();
    for (int out = tid; out < 128 * 50; out += 256) {
        int c = out / 50, j = out - c * 50;
        const float* w = cw1 + c * TOTALC;
        const float* r0 = xs + (2 * j) * TOTALC;
        const float* r1 = xs + (2 * j + 1) * TOTALC;
        float a0 = cb1[c], a1 = a0;
#pragma unroll 4
        for (int t = 0; t < TOTALC; t++) {
            float wv = w[t];
            a0 = fmaf(r0[t], wv, a0);
            a1 = fmaf(r1[t], wv, a1);
        }
        g_p1[(g * 128 + c) * 50 + j] = fmaxf(fmaxf(a0, a1), 0.0f);
    }
}

// ---------------- conv2 (128->64, k=5) + relu ----------------
__global__ void k_conv2(const float* __restrict__ cw2, const float* __restrict__ cb2) {
    __shared__ float ps[128 * 50];
    int g = blockIdx.x, tid = threadIdx.x;  // 256 threads
    for (int i = tid; i < 128 * 50; i += 256) ps[i] = g_p1[g * 6400 + i];
    __syncthreads();
    for (int out = tid; out < 64 * 46; out += 256) {
        int o = out / 46, j = out - o * 46;
        const float* w = cw2 + o * 640;
        float acc = cb2[o];
#pragma unroll 4
        for (int i = 0; i < 128; i++) {
            const float* pr = ps + i * 50 + j;
            const float* wr = w + i * 5;
            acc = fmaf(pr[0], wr[0], acc);
            acc = fmaf(pr[1], wr[1], acc);
            acc = fmaf(pr[2], wr[2], acc);
            acc = fmaf(pr[3], wr[3], acc);
            acc = fmaf(pr[4], wr[4], acc);
        }
        g_c2f[g * 2944 + o * 46 + j] = fmaxf(acc, 0.0f);
    }
}

// ---------------- fc1 + relu (4 graphs per block) ----------------
__global__ void k_fc1(const float* __restrict__ fw1, const float* __restrict__ fb1) {
    __shared__ float cs[4 * 2944];
    int gb = blockIdx.x, tid = threadIdx.x;  // 128 threads
    int g0 = gb * 4;
    for (int i = tid; i < 4 * 2944; i += 128) {
        int g = g0 + i / 2944;
        cs[i] = (g < NGRAPH) ? g_c2f[g * 2944 + (i % 2944)] : 0.0f;
    }
    __syncthreads();
    const float4* wr = reinterpret_cast<const float4*>(fw1 + (size_t)tid * 2944);
    const float4* c0 = reinterpret_cast<const float4*>(cs);
    const float4* c1 = reinterpret_cast<const float4*>(cs + 2944);
    const float4* c2 = reinterpret_cast<const float4*>(cs + 2 * 2944);
    const float4* c3 = reinterpret_cast<const float4*>(cs + 3 * 2944);
    float a0 = 0, a1 = 0, a2 = 0, a3 = 0;
    for (int d = 0; d < 736; d++) {
        float4 w = wr[d];
        float4 v;
        v = c0[d]; a0 += w.x * v.x + w.y * v.y + w.z * v.z + w.w * v.w;
        v = c1[d]; a1 += w.x * v.x + w.y * v.y + w.z * v.z + w.w * v.w;
        v = c2[d]; a2 += w.x * v.x + w.y * v.y + w.z * v.z + w.w * v.w;
        v = c3[d]; a3 += w.x * v.x + w.y * v.y + w.z * v.z + w.w * v.w;
    }
    float bb = fb1[tid];
    if (g0 + 0 < NGRAPH) g_hfc[(g0 + 0) * 128 + tid] = fmaxf(a0 + bb, 0.0f);
    if (g0 + 1 < NGRAPH) g_hfc[(g0 + 1) * 128 + tid] = fmaxf(a1 + bb, 0.0f);
    if (g0 + 2 < NGRAPH) g_hfc[(g0 + 2) * 128 + tid] = fmaxf(a2 + bb, 0.0f);
    if (g0 + 3 < NGRAPH) g_hfc[(g0 + 3) * 128 + tid] = fmaxf(a3 + bb, 0.0f);
}

// ---------------- fc3 + log_softmax ----------------
__global__ void k_fc3(const float* __restrict__ fw3, const float* __restrict__ fb3,
                      float* __restrict__ out) {
    int b = blockIdx.x * 256 + threadIdx.x;
    if (b >= NGRAPH) return;
    float l0 = fb3[0], l1 = fb3[1];
#pragma unroll 4
    for (int d = 0; d < 128; d++) {
        float h = g_hfc[b * 128 + d];
        l0 = fmaf(h, fw3[d], l0);
        l1 = fmaf(h, fw3[128 + d], l1);
    }
    float m = fmaxf(l0, l1);
    float lse = m + logf(expf(l0 - m) + expf(l1 - m));
    out[b * 2 + 0] = l0 - lse;
    out[b * 2 + 1] = l1 - lse;
}

// ---------------- launch ----------------
extern "C" void kernel_launch(void* const* d_in, const int* in_sizes, int n_in,
                              void* d_out, int out_size) {
    const float* x   = (const float*)d_in[0];
    const int*   ei  = (const int*)d_in[1];
    const int*   src = ei;
    const int*   dst = ei + N_EDGES;
    const float* W1 = (const float*)d_in[3];  const float* b1 = (const float*)d_in[4];
    const float* W2 = (const float*)d_in[5];  const float* b2 = (const float*)d_in[6];
    const float* W3 = (const float*)d_in[7];  const float* b3 = (const float*)d_in[8];
    const float* W4 = (const float*)d_in[9];  const float* b4 = (const float*)d_in[10];
    const float* cw1 = (const float*)d_in[11]; const float* cb1 = (const float*)d_in[12];
    const float* cw2 = (const float*)d_in[13]; const float* cb2 = (const float*)d_in[14];
    const float* fw1 = (const float*)d_in[15]; const float* fb1 = (const float*)d_in[16];
    const float* fw3 = (const float*)d_in[17]; const float* fb3 = (const float*)d_in[18];
    float* out = (float*)d_out;

    const int TB = 256;
    const int gN  = (N_NODES + TB - 1) / TB;     // 391
    const int gE  = (N_EDGES + TB - 1) / TB;     // 12500
    const int gG8 = (N_NODES + 7) / 8;           // 12500

    // CSR build
    k_hist_init<<<gN, TB>>>();
    k_hist<<<gE, TB>>>(dst);
    k_scanA<<<NBLK_SCAN, SCAN_BLK>>>();
    k_scanB<<<1, 128>>>();
    k_scanC<<<gN, TB>>>();
    k_fill<<<gE, TB>>>(src, dst);

    // layer 1: h = X@W1; x1 = tanh(A h + deginv h + b1)
    k_gemm1<<<gG8, TB>>>(x, W1);
    k_gather<<<gG8, TB>>>(0, 1, b1);
    // layer 2: z = A x1 + deginv x1; x2 = tanh(z@W2 + b2)
    k_gather<<<gG8, TB>>>(1, 0, nullptr);
    k_zgemm<<<gG8, TB>>>(2, W2, b2, nullptr, nullptr);
    // layers 3+4 share z of x2: x3 = tanh(z@W3+b3), score = tanh(z.W4+b4)
    k_gather<<<gG8, TB>>>(2, 0, nullptr);
    k_zgemm<<<gG8, TB>>>(3, W3, b3, W4, b4);

    // tail
    k_sortpool<<<NGRAPH, TB>>>();
    k_conv1pool<<<NGRAPH, TB>>>(cw1, cb1);
    k_conv2<<<NGRAPH, TB>>>(cw2, cb2);
    k_fc1<<<(NGRAPH + 3) / 4, 128>>>(fw1, fb1);
    k_fc3<<<1, TB>>>(fw3, fb3, out);
}

// round 4
// speedup vs baseline: 1.4320x; 1.2967x over previous
#include <cuda_runtime.h>
#include <math.h>

#define N_NODES 100000
#define N_EDGES 3200000
#define DIMC 32
#define INDIM 128
#define NGRAPH 250
#define NPER 400
#define KTOP 100
#define TOTALC 97
#define SCAN_BLK 1024
#define NBLK_SCAN ((N_NODES + SCAN_BLK - 1) / SCAN_BLK)   // 98

// ---------------- device scratch ----------------
__device__ int   g_cnt[N_NODES];
__device__ int   g_fill[N_NODES];
__device__ int   g_off[N_NODES + 1];
__device__ int   g_bsum[NBLK_SCAN];
__device__ float g_dis[N_NODES];
__device__ float g_deginv[N_NODES];
__device__ int2  g_csr[N_EDGES];          // {src, coef bits}
__device__ float g_h[N_NODES * DIMC];
__device__ float g_x1[N_NODES * DIMC];
__device__ float g_x2[N_NODES * DIMC];
__device__ float g_x3[N_NODES * DIMC];
__device__ float g_score[N_NODES];
__device__ int   g_topk[NGRAPH * KTOP];
__device__ float g_p1[NGRAPH * 128 * 50];
__device__ float g_c2f[NGRAPH * 2944];
__device__ float g_hfc[NGRAPH * 128];

// ---------------- CSR build ----------------
__global__ void k_hist_init() {
    int i = blockIdx.x * 256 + threadIdx.x;
    if (i < N_NODES) g_cnt[i] = 0;
}
__global__ void k_hist(const int* __restrict__ dst) {
    int e = blockIdx.x * 256 + threadIdx.x;
    if (e < N_EDGES) atomicAdd(&g_cnt[dst[e]], 1);
}
__global__ void k_scanA() {
    __shared__ int s[SCAN_BLK];
    int tid = threadIdx.x;
    int i = blockIdx.x * SCAN_BLK + tid;
    int v = (i < N_NODES) ? g_cnt[i] : 0;
    s[tid] = v;
    __syncthreads();
    for (int o = 1; o < SCAN_BLK; o <<= 1) {
        int t = (tid >= o) ? s[tid - o] : 0;
        __syncthreads();
        s[tid] += t;
        __syncthreads();
    }
    if (i < N_NODES) g_off[i] = s[tid] - v;
    if (tid == SCAN_BLK - 1) g_bsum[blockIdx.x] = s[tid];
}
__global__ void k_scanB() {
    __shared__ int bs[NBLK_SCAN];
    int tid = threadIdx.x;
    if (tid < NBLK_SCAN) bs[tid] = g_bsum[tid];
    __syncthreads();
    if (tid == 0) {
        int run = 0;
        for (int b = 0; b < NBLK_SCAN; b++) { int t = bs[b]; bs[b] = run; run += t; }
        g_off[N_NODES] = N_EDGES;
    }
    __syncthreads();
    if (tid < NBLK_SCAN) g_bsum[tid] = bs[tid];
}
__global__ void k_scanC() {
    int i = blockIdx.x * 256 + threadIdx.x;
    if (i >= N_NODES) return;
    g_off[i] += g_bsum[i / SCAN_BLK];
    g_fill[i] = 0;
    float d = (float)g_cnt[i] + 1.0f;
    g_dis[i] = rsqrtf(d);
    g_deginv[i] = 1.0f / d;
}
__global__ void k_fill(const int* __restrict__ src, const int* __restrict__ dst) {
    int e = blockIdx.x * 256 + threadIdx.x;
    if (e >= N_EDGES) return;
    int s = src[e], d = dst[e];
    int pos = g_off[d] + atomicAdd(&g_fill[d], 1);
    float c = g_dis[s] * g_dis[d];
    g_csr[pos] = make_int2(s, __float_as_int(c));
}

// ---------------- h = X @ W1 (128 -> 32) ----------------
__global__ void k_gemm1(const float* __restrict__ X, const float* __restrict__ W) {
    __shared__ float Ws[INDIM * DIMC];
    int tid = threadIdx.x;
    for (int i = tid; i < INDIM * DIMC; i += 256) Ws[i] = W[i];
    __syncthreads();
    int node = blockIdx.x * 8 + (tid >> 5);
    if (node >= N_NODES) return;
    int dim = tid & 31;
    const float* xr = X + (size_t)node * INDIM;
    float acc = 0.0f;
#pragma unroll 8
    for (int k = 0; k < INDIM; k++) acc = fmaf(xr[k], Ws[k * DIMC + dim], acc);
    g_h[node * DIMC + dim] = acc;
}

// ---------------- CSR gather (4 edges/warp, float4) + fused transform ----------------
// warp per node; lanes = 4 edge-groups x 8 sub-lanes; acc covers dims sub*4..sub*4+3.
// layer 1: out = tanh(z + b)          -> g_x1
// layer 2: out = tanh(z @ W + b)      -> g_x2
// layer 3: out = tanh(z @ W + b)      -> g_x3, plus score = tanh(z . W4 + b4)
__global__ void k_gather(int layer, const float* __restrict__ W,
                         const float* __restrict__ b,
                         const float* __restrict__ W4, const float* __restrict__ b4) {
    __shared__ float Ws[DIMC * DIMC];
    int tid = threadIdx.x;
    if (layer >= 2) {
        for (int i = tid; i < DIMC * DIMC; i += 256) Ws[i] = W[i];
        __syncthreads();
    }
    const float* __restrict__ X = (layer == 1) ? g_h : (layer == 2 ? g_x1 : g_x2);
    int node = blockIdx.x * 8 + (tid >> 5);
    if (node >= N_NODES) return;
    int lane = tid & 31;
    int grp = lane >> 3, sub = lane & 7;
    int beg = g_off[node], end = g_off[node + 1];

    float4 acc = make_float4(0.f, 0.f, 0.f, 0.f);
    for (int base = beg; base < end; base += 4) {
        int eidx = base + grp;
        int s = 0; float c = 0.0f;
        if (eidx < end) {
            int2 ec = g_csr[eidx];
            s = ec.x; c = __int_as_float(ec.y);
        }
        const float4 xv = *reinterpret_cast<const float4*>(&X[s * DIMC + sub * 4]);
        acc.x = fmaf(c, xv.x, acc.x);
        acc.y = fmaf(c, xv.y, acc.y);
        acc.z = fmaf(c, xv.z, acc.z);
        acc.w = fmaf(c, xv.w, acc.w);
    }
    // butterfly over the two group bits -> every lane holds the total
#pragma unroll
    for (int off = 8; off <= 16; off <<= 1) {
        acc.x += __shfl_xor_sync(0xffffffffu, acc.x, off);
        acc.y += __shfl_xor_sync(0xffffffffu, acc.y, off);
        acc.z += __shfl_xor_sync(0xffffffffu, acc.z, off);
        acc.w += __shfl_xor_sync(0xffffffffu, acc.w, off);
    }
    // self-loop term
    float dinv = g_deginv[node];
    const float4 xself = *reinterpret_cast<const float4*>(&X[node * DIMC + sub * 4]);
    acc.x = fmaf(xself.x, dinv, acc.x);
    acc.y = fmaf(xself.y, dinv, acc.y);
    acc.z = fmaf(xself.z, dinv, acc.z);
    acc.w = fmaf(xself.w, dinv, acc.w);

    if (layer == 1) {
        if (grp == 0) {
            float4 o;
            o.x = tanhf(acc.x + b[sub * 4 + 0]);
            o.y = tanhf(acc.y + b[sub * 4 + 1]);
            o.z = tanhf(acc.z + b[sub * 4 + 2]);
            o.w = tanhf(acc.w + b[sub * 4 + 3]);
            *reinterpret_cast<float4*>(&g_x1[node * DIMC + sub * 4]) = o;
        }
        return;
    }

    // transform: out[lane] = sum_j z[j] * W[j][lane]
    float outacc = 0.0f;
#pragma unroll
    for (int jb = 0; jb < 8; jb++) {
        float z0 = __shfl_sync(0xffffffffu, acc.x, jb);
        float z1 = __shfl_sync(0xffffffffu, acc.y, jb);
        float z2 = __shfl_sync(0xffffffffu, acc.z, jb);
        float z3 = __shfl_sync(0xffffffffu, acc.w, jb);
        outacc = fmaf(z0, Ws[(jb * 4 + 0) * DIMC + lane], outacc);
        outacc = fmaf(z1, Ws[(jb * 4 + 1) * DIMC + lane], outacc);
        outacc = fmaf(z2, Ws[(jb * 4 + 2) * DIMC + lane], outacc);
        outacc = fmaf(z3, Ws[(jb * 4 + 3) * DIMC + lane], outacc);
    }
    float o = tanhf(outacc + b[lane]);
    if (layer == 2) {
        g_x2[node * DIMC + lane] = o;
    } else {
        g_x3[node * DIMC + lane] = o;
        float t = acc.x * W4[sub * 4 + 0] + acc.y * W4[sub * 4 + 1]
                + acc.z * W4[sub * 4 + 2] + acc.w * W4[sub * 4 + 3];
        t += __shfl_xor_sync(0xffffffffu, t, 1);
        t += __shfl_xor_sync(0xffffffffu, t, 2);
        t += __shfl_xor_sync(0xffffffffu, t, 4);
        if (lane == 0) g_score[node] = tanhf(t + b4[0]);
    }
}

// ---------------- sort pooling: per-graph bitonic-512, top-100 ----------------
__global__ void k_sortpool() {
    __shared__ float s[512];
    __shared__ int   si[512];
    int g = blockIdx.x, tid = threadIdx.x;  // 256 threads
    for (int i = tid; i < 512; i += 256) {
        if (i < NPER) { s[i] = g_score[g * NPER + i]; si[i] = i; }
        else          { s[i] = __int_as_float(0xff800000); si[i] = 0x7FFFFFFF; }
    }
    __syncthreads();
    for (int k = 2; k <= 512; k <<= 1) {
        for (int j = k >> 1; j > 0; j >>= 1) {
            for (int i = tid; i < 512; i += 256) {
                int ixj = i ^ j;
                if (ixj > i) {
                    float a = s[i], bb = s[ixj];
                    int ia = si[i], ib = si[ixj];
                    bool before = (a > bb) || (a == bb && ia < ib);
                    bool dirDesc = ((i & k) == 0);
                    if (dirDesc ? !before : before) {
                        s[i] = bb; s[ixj] = a; si[i] = ib; si[ixj] = ia;
                    }
                }
            }
            __syncthreads();
        }
    }
    if (tid < KTOP) g_topk[g * KTOP + tid] = g * NPER + si[tid];
}

// ---------------- conv1 + relu + maxpool(2,2), 4 channels/thread ----------------
__global__ void k_conv1pool(const float* __restrict__ cw1, const float* __restrict__ cb1) {
    __shared__ float xs[KTOP * TOTALC];
    int g = blockIdx.x, tid = threadIdx.x;  // 256 threads
    for (int i = tid; i < KTOP * TOTALC; i += 256) {
        int kslot = i / TOTALC, t = i - kslot * TOTALC;
        int n = g_topk[g * KTOP + kslot];
        float v;
        if (t < 32)      v = g_x1[n * DIMC + t];
        else if (t < 64) v = g_x2[n * DIMC + t - 32];
        else if (t < 96) v = g_x3[n * DIMC + t - 64];
        else             v = g_score[n];
        xs[i] = v;
    }
    __syncthreads();
    // items: 32 channel-bases x 50 pooled slots
    for (int item = tid; item < 32 * 50; item += 256) {
        int cb = item / 50, j = item - cb * 50;
        const float* r0 = xs + (2 * j) * TOTALC;
        const float* r1 = r0 + TOTALC;
        float a[8];
#pragma unroll
        for (int q = 0; q < 4; q++) { float bb = cb1[cb + q * 32]; a[q] = bb; a[4 + q] = bb; }
#pragma unroll 2
        for (int t = 0; t < TOTALC; t++) {
            float v0 = r0[t], v1 = r1[t];
#pragma unroll
            for (int q = 0; q < 4; q++) {
                float wv = cw1[(cb + q * 32) * TOTALC + t];
                a[q]     = fmaf(v0, wv, a[q]);
                a[4 + q] = fmaf(v1, wv, a[4 + q]);
            }
        }
#pragma unroll
        for (int q = 0; q < 4; q++)
            g_p1[(g * 128 + cb + q * 32) * 50 + j] = fmaxf(fmaxf(a[q], a[4 + q]), 0.0f);
    }
}

// ---------------- conv2 (128->64, k=5) + relu, 4 channels/thread ----------------
__global__ void k_conv2(const float* __restrict__ cw2, const float* __restrict__ cb2) {
    __shared__ float ps[128 * 50];
    int g = blockIdx.x, tid = threadIdx.x;  // 256 threads
    for (int i = tid; i < 128 * 50; i += 256) ps[i] = g_p1[g * 6400 + i];
    __syncthreads();
    for (int item = tid; item < 16 * 46; item += 256) {
        int ob = item / 46, j = item - ob * 46;
        float a0 = cb2[ob], a1 = cb2[ob + 16], a2 = cb2[ob + 32], a3 = cb2[ob + 48];
        const float* w0 = cw2 + (ob)      * 640;
        const float* w1 = cw2 + (ob + 16) * 640;
        const float* w2 = cw2 + (ob + 32) * 640;
        const float* w3 = cw2 + (ob + 48) * 640;
#pragma unroll 2
        for (int i = 0; i < 128; i++) {
            const float* pr = ps + i * 50 + j;
            float p0 = pr[0], p1 = pr[1], p2 = pr[2], p3 = pr[3], p4 = pr[4];
            const float* q0 = w0 + i * 5;
            const float* q1 = w1 + i * 5;
            const float* q2 = w2 + i * 5;
            const float* q3 = w3 + i * 5;
            a0 = fmaf(p0, q0[0], a0); a0 = fmaf(p1, q0[1], a0); a0 = fmaf(p2, q0[2], a0);
            a0 = fmaf(p3, q0[3], a0); a0 = fmaf(p4, q0[4], a0);
            a1 = fmaf(p0, q1[0], a1); a1 = fmaf(p1, q1[1], a1); a1 = fmaf(p2, q1[2], a1);
            a1 = fmaf(p3, q1[3], a1); a1 = fmaf(p4, q1[4], a1);
            a2 = fmaf(p0, q2[0], a2); a2 = fmaf(p1, q2[1], a2); a2 = fmaf(p2, q2[2], a2);
            a2 = fmaf(p3, q2[3], a2); a2 = fmaf(p4, q2[4], a2);
            a3 = fmaf(p0, q3[0], a3); a3 = fmaf(p1, q3[1], a3); a3 = fmaf(p2, q3[2], a3);
            a3 = fmaf(p3, q3[3], a3); a3 = fmaf(p4, q3[4], a3);
        }
        g_c2f[g * 2944 + (ob)      * 46 + j] = fmaxf(a0, 0.0f);
        g_c2f[g * 2944 + (ob + 16) * 46 + j] = fmaxf(a1, 0.0f);
        g_c2f[g * 2944 + (ob + 32) * 46 + j] = fmaxf(a2, 0.0f);
        g_c2f[g * 2944 + (ob + 48) * 46 + j] = fmaxf(a3, 0.0f);
    }
}

// ---------------- fc1 + relu (4 graphs per block) ----------------
__global__ void k_fc1(const float* __restrict__ fw1, const float* __restrict__ fb1) {
    __shared__ float cs[4 * 2944];
    int gb = blockIdx.x, tid = threadIdx.x;  // 128 threads
    int g0 = gb * 4;
    for (int i = tid; i < 4 * 2944; i += 128) {
        int g = g0 + i / 2944;
        cs[i] = (g < NGRAPH) ? g_c2f[g * 2944 + (i % 2944)] : 0.0f;
    }
    __syncthreads();
    const float4* wr = reinterpret_cast<const float4*>(fw1 + (size_t)tid * 2944);
    const float4* c0 = reinterpret_cast<const float4*>(cs);
    const float4* c1 = reinterpret_cast<const float4*>(cs + 2944);
    const float4* c2 = reinterpret_cast<const float4*>(cs + 2 * 2944);
    const float4* c3 = reinterpret_cast<const float4*>(cs + 3 * 2944);
    float a0 = 0, a1 = 0, a2 = 0, a3 = 0;
    for (int d = 0; d < 736; d++) {
        float4 w = wr[d];
        float4 v;
        v = c0[d]; a0 += w.x * v.x + w.y * v.y + w.z * v.z + w.w * v.w;
        v = c1[d]; a1 += w.x * v.x + w.y * v.y + w.z * v.z + w.w * v.w;
        v = c2[d]; a2 += w.x * v.x + w.y * v.y + w.z * v.z + w.w * v.w;
        v = c3[d]; a3 += w.x * v.x + w.y * v.y + w.z * v.z + w.w * v.w;
    }
    float bb = fb1[tid];
    if (g0 + 0 < NGRAPH) g_hfc[(g0 + 0) * 128 + tid] = fmaxf(a0 + bb, 0.0f);
    if (g0 + 1 < NGRAPH) g_hfc[(g0 + 1) * 128 + tid] = fmaxf(a1 + bb, 0.0f);
    if (g0 + 2 < NGRAPH) g_hfc[(g0 + 2) * 128 + tid] = fmaxf(a2 + bb, 0.0f);
    if (g0 + 3 < NGRAPH) g_hfc[(g0 + 3) * 128 + tid] = fmaxf(a3 + bb, 0.0f);
}

// ---------------- fc3 + log_softmax ----------------
__global__ void k_fc3(const float* __restrict__ fw3, const float* __restrict__ fb3,
                      float* __restrict__ out) {
    int b = blockIdx.x * 256 + threadIdx.x;
    if (b >= NGRAPH) return;
    float l0 = fb3[0], l1 = fb3[1];
#pragma unroll 4
    for (int d = 0; d < 128; d++) {
        float h = g_hfc[b * 128 + d];
        l0 = fmaf(h, fw3[d], l0);
        l1 = fmaf(h, fw3[128 + d], l1);
    }
    float m = fmaxf(l0, l1);
    float lse = m + logf(expf(l0 - m) + expf(l1 - m));
    out[b * 2 + 0] = l0 - lse;
    out[b * 2 + 1] = l1 - lse;
}

// ---------------- launch ----------------
extern "C" void kernel_launch(void* const* d_in, const int* in_sizes, int n_in,
                              void* d_out, int out_size) {
    const float* x   = (const float*)d_in[0];
    const int*   ei  = (const int*)d_in[1];
    const int*   src = ei;
    const int*   dst = ei + N_EDGES;
    const float* W1 = (const float*)d_in[3];  const float* b1 = (const float*)d_in[4];
    const float* W2 = (const float*)d_in[5];  const float* b2 = (const float*)d_in[6];
    const float* W3 = (const float*)d_in[7];  const float* b3 = (const float*)d_in[8];
    const float* W4 = (const float*)d_in[9];  const float* b4 = (const float*)d_in[10];
    const float* cw1 = (const float*)d_in[11]; const float* cb1 = (const float*)d_in[12];
    const float* cw2 = (const float*)d_in[13]; const float* cb2 = (const float*)d_in[14];
    const float* fw1 = (const float*)d_in[15]; const float* fb1 = (const float*)d_in[16];
    const float* fw3 = (const float*)d_in[17]; const float* fb3 = (const float*)d_in[18];
    float* out = (float*)d_out;

    const int TB = 256;
    const int gN  = (N_NODES + TB - 1) / TB;     // 391
    const int gE  = (N_EDGES + TB - 1) / TB;     // 12500
    const int gG8 = (N_NODES + 7) / 8;           // 12500

    // CSR build (k_gemm1 is CSR-independent; placed at launch index 3 so the
    // harness's ncu capture (-s 5 -c 1 -> 4th launch) profiles a heavy kernel)
    k_hist_init<<<gN, TB>>>();                       // 0
    k_hist<<<gE, TB>>>(dst);                         // 1
    k_scanA<<<NBLK_SCAN, SCAN_BLK>>>();              // 2
    k_gemm1<<<gG8, TB>>>(x, W1);                     // 3  <- profiled
    k_scanB<<<1, 128>>>();                           // 4
    k_scanC<<<gN, TB>>>();                           // 5
    k_fill<<<gE, TB>>>(src, dst);                    // 6

    // layer 1: x1 = tanh(A h + deginv h + b1)
    k_gather<<<gG8, TB>>>(1, nullptr, b1, nullptr, nullptr);
    // layer 2: x2 = tanh((A x1 + deginv x1) @ W2 + b2)
    k_gather<<<gG8, TB>>>(2, W2, b2, nullptr, nullptr);
    // layers 3+4 share z of x2
    k_gather<<<gG8, TB>>>(3, W3, b3, W4, b4);

    // tail
    k_sortpool<<<NGRAPH, TB>>>();
    k_conv1pool<<<NGRAPH, TB>>>(cw1, cb1);
    k_conv2<<<NGRAPH, TB>>>(cw2, cb2);
    k_fc1<<<(NGRAPH + 3) / 4, 128>>>(fw1, fb1);
    k_fc3<<<1, TB>>>(fw3, fb3, out);
}

// round 5
// speedup vs baseline: 1.6131x; 1.1265x over previous
#include <cuda_runtime.h>
#include <math.h>

#define N_NODES 100000
#define N_EDGES 3200000
#define DIMC 32
#define INDIM 128
#define NGRAPH 250
#define NPER 400
#define KTOP 100
#define TOTALC 97
#define SCAN_BLK 1024
#define NBLK_SCAN ((N_NODES + SCAN_BLK - 1) / SCAN_BLK)   // 98
#define GM_NODES 32

// ---------------- device scratch ----------------
__device__ int   g_cnt[N_NODES];
__device__ int   g_fill[N_NODES];
__device__ int   g_off[N_NODES + 1];
__device__ int   g_bsum[NBLK_SCAN];
__device__ float g_dis[N_NODES];
__device__ float g_deginv[N_NODES];
__device__ int2  g_csr[N_EDGES];          // {src, coef bits}
__device__ float g_h[N_NODES * DIMC];
__device__ float g_x1[N_NODES * DIMC];
__device__ float g_x2[N_NODES * DIMC];
__device__ float g_x3[N_NODES * DIMC];
__device__ float g_score[N_NODES];
__device__ int   g_topk[NGRAPH * KTOP];
__device__ float g_p1[NGRAPH * 128 * 50];
__device__ float g_c2f[NGRAPH * 2944];
__device__ float g_hfc[NGRAPH * 128];

// ---------------- CSR build ----------------
__global__ void k_hist_init() {
    int i = blockIdx.x * 256 + threadIdx.x;
    if (i < N_NODES) g_cnt[i] = 0;
}
__global__ void k_hist(const int* __restrict__ dst) {
    int e = blockIdx.x * 256 + threadIdx.x;
    if (e < N_EDGES) atomicAdd(&g_cnt[dst[e]], 1);
}
__global__ void k_scanA() {
    __shared__ int s[SCAN_BLK];
    int tid = threadIdx.x;
    int i = blockIdx.x * SCAN_BLK + tid;
    int v = (i < N_NODES) ? g_cnt[i] : 0;
    s[tid] = v;
    __syncthreads();
    for (int o = 1; o < SCAN_BLK; o <<= 1) {
        int t = (tid >= o) ? s[tid - o] : 0;
        __syncthreads();
        s[tid] += t;
        __syncthreads();
    }
    if (i < N_NODES) g_off[i] = s[tid] - v;
    if (tid == SCAN_BLK - 1) g_bsum[blockIdx.x] = s[tid];
}
__global__ void k_scanB() {
    __shared__ int bs[NBLK_SCAN];
    int tid = threadIdx.x;
    if (tid < NBLK_SCAN) bs[tid] = g_bsum[tid];
    __syncthreads();
    if (tid == 0) {
        int run = 0;
        for (int b = 0; b < NBLK_SCAN; b++) { int t = bs[b]; bs[b] = run; run += t; }
        g_off[N_NODES] = N_EDGES;
    }
    __syncthreads();
    if (tid < NBLK_SCAN) g_bsum[tid] = bs[tid];
}
__global__ void k_scanC() {
    int i = blockIdx.x * 256 + threadIdx.x;
    if (i >= N_NODES) return;
    g_off[i] += g_bsum[i / SCAN_BLK];
    g_fill[i] = 0;
    float d = (float)g_cnt[i] + 1.0f;
    g_dis[i] = rsqrtf(d);
    g_deginv[i] = 1.0f / d;
}
__global__ void k_fill(const int* __restrict__ src, const int* __restrict__ dst) {
    int e = blockIdx.x * 256 + threadIdx.x;
    if (e >= N_EDGES) return;
    int s = src[e], d = dst[e];
    int pos = g_off[d] + atomicAdd(&g_fill[d], 1);
    float c = g_dis[s] * g_dis[d];
    g_csr[pos] = make_int2(s, __float_as_int(c));
}

// ---------------- h = X @ W1 (128 -> 32), tiled GEMM ----------------
// block = 32 nodes x 32 dims, 256 threads, 4 outputs/thread.
__global__ void k_gemm1(const float* __restrict__ X, const float* __restrict__ W) {
    __shared__ float Xs[GM_NODES * INDIM];   // 16 KB
    __shared__ float Ws[INDIM * DIMC];       // 16 KB
    int tid = threadIdx.x;
    int nbase = blockIdx.x * GM_NODES;       // 3125 blocks, exact

    const float4* Wg = reinterpret_cast<const float4*>(W);
    float4* Ws4 = reinterpret_cast<float4*>(Ws);
    for (int i = tid; i < INDIM * DIMC / 4; i += 256) Ws4[i] = Wg[i];
    const float4* Xg = reinterpret_cast<const float4*>(X + (size_t)nbase * INDIM);
    float4* Xs4 = reinterpret_cast<float4*>(Xs);
    for (int i = tid; i < GM_NODES * INDIM / 4; i += 256) Xs4[i] = Xg[i];
    __syncthreads();

    int dim = tid & 31, nq = tid >> 5;       // nq = 0..7
    const float* xr0 = Xs + (nq * 4 + 0) * INDIM;
    const float* xr1 = Xs + (nq * 4 + 1) * INDIM;
    const float* xr2 = Xs + (nq * 4 + 2) * INDIM;
    const float* xr3 = Xs + (nq * 4 + 3) * INDIM;
    float a0 = 0.f, a1 = 0.f, a2 = 0.f, a3 = 0.f;
#pragma unroll 4
    for (int kb = 0; kb < INDIM; kb += 4) {
        float w0 = Ws[(kb + 0) * DIMC + dim];
        float w1 = Ws[(kb + 1) * DIMC + dim];
        float w2 = Ws[(kb + 2) * DIMC + dim];
        float w3 = Ws[(kb + 3) * DIMC + dim];
        float4 v0 = *reinterpret_cast<const float4*>(xr0 + kb);
        float4 v1 = *reinterpret_cast<const float4*>(xr1 + kb);
        float4 v2 = *reinterpret_cast<const float4*>(xr2 + kb);
        float4 v3 = *reinterpret_cast<const float4*>(xr3 + kb);
        a0 = fmaf(v0.x, w0, a0); a0 = fmaf(v0.y, w1, a0);
        a0 = fmaf(v0.z, w2, a0); a0 = fmaf(v0.w, w3, a0);
        a1 = fmaf(v1.x, w0, a1); a1 = fmaf(v1.y, w1, a1);
        a1 = fmaf(v1.z, w2, a1); a1 = fmaf(v1.w, w3, a1);
        a2 = fmaf(v2.x, w0, a2); a2 = fmaf(v2.y, w1, a2);
        a2 = fmaf(v2.z, w2, a2); a2 = fmaf(v2.w, w3, a2);
        a3 = fmaf(v3.x, w0, a3); a3 = fmaf(v3.y, w1, a3);
        a3 = fmaf(v3.z, w2, a3); a3 = fmaf(v3.w, w3, a3);
    }
    int nb = nbase + nq * 4;
    g_h[(nb + 0) * DIMC + dim] = a0;
    g_h[(nb + 1) * DIMC + dim] = a1;
    g_h[(nb + 2) * DIMC + dim] = a2;
    g_h[(nb + 3) * DIMC + dim] = a3;
}

// ---------------- CSR gather (8 edges/warp-iter, float4) + fused transform ----------------
__global__ void k_gather(int layer, const float* __restrict__ W,
                         const float* __restrict__ b,
                         const float* __restrict__ W4, const float* __restrict__ b4) {
    __shared__ float Ws[DIMC * DIMC];
    int tid = threadIdx.x;
    if (layer >= 2) {
        for (int i = tid; i < DIMC * DIMC; i += 256) Ws[i] = W[i];
        __syncthreads();
    }
    const float* __restrict__ X = (layer == 1) ? g_h : (layer == 2 ? g_x1 : g_x2);
    int node = blockIdx.x * 8 + (tid >> 5);
    if (node >= N_NODES) return;
    int lane = tid & 31;
    int grp = lane >> 3, sub = lane & 7;
    int beg = g_off[node], end = g_off[node + 1];

    float4 acc = make_float4(0.f, 0.f, 0.f, 0.f);
    for (int base = beg; base < end; base += 8) {
        int e0 = base + grp, e1 = base + 4 + grp;
        int s0 = 0, s1 = 0; float c0 = 0.f, c1 = 0.f;
        if (e0 < end) { int2 t = g_csr[e0]; s0 = t.x; c0 = __int_as_float(t.y); }
        if (e1 < end) { int2 t = g_csr[e1]; s1 = t.x; c1 = __int_as_float(t.y); }
        const float4 v0 = *reinterpret_cast<const float4*>(&X[s0 * DIMC + sub * 4]);
        const float4 v1 = *reinterpret_cast<const float4*>(&X[s1 * DIMC + sub * 4]);
        acc.x = fmaf(c0, v0.x, fmaf(c1, v1.x, acc.x));
        acc.y = fmaf(c0, v0.y, fmaf(c1, v1.y, acc.y));
        acc.z = fmaf(c0, v0.z, fmaf(c1, v1.z, acc.z));
        acc.w = fmaf(c0, v0.w, fmaf(c1, v1.w, acc.w));
    }
#pragma unroll
    for (int off = 8; off <= 16; off <<= 1) {
        acc.x += __shfl_xor_sync(0xffffffffu, acc.x, off);
        acc.y += __shfl_xor_sync(0xffffffffu, acc.y, off);
        acc.z += __shfl_xor_sync(0xffffffffu, acc.z, off);
        acc.w += __shfl_xor_sync(0xffffffffu, acc.w, off);
    }
    float dinv = g_deginv[node];
    const float4 xself = *reinterpret_cast<const float4*>(&X[node * DIMC + sub * 4]);
    acc.x = fmaf(xself.x, dinv, acc.x);
    acc.y = fmaf(xself.y, dinv, acc.y);
    acc.z = fmaf(xself.z, dinv, acc.z);
    acc.w = fmaf(xself.w, dinv, acc.w);

    if (layer == 1) {
        if (grp == 0) {
            float4 o;
            o.x = tanhf(acc.x + b[sub * 4 + 0]);
            o.y = tanhf(acc.y + b[sub * 4 + 1]);
            o.z = tanhf(acc.z + b[sub * 4 + 2]);
            o.w = tanhf(acc.w + b[sub * 4 + 3]);
            *reinterpret_cast<float4*>(&g_x1[node * DIMC + sub * 4]) = o;
        }
        return;
    }

    float outacc = 0.0f;
#pragma unroll
    for (int jb = 0; jb < 8; jb++) {
        float z0 = __shfl_sync(0xffffffffu, acc.x, jb);
        float z1 = __shfl_sync(0xffffffffu, acc.y, jb);
        float z2 = __shfl_sync(0xffffffffu, acc.z, jb);
        float z3 = __shfl_sync(0xffffffffu, acc.w, jb);
        outacc = fmaf(z0, Ws[(jb * 4 + 0) * DIMC + lane], outacc);
        outacc = fmaf(z1, Ws[(jb * 4 + 1) * DIMC + lane], outacc);
        outacc = fmaf(z2, Ws[(jb * 4 + 2) * DIMC + lane], outacc);
        outacc = fmaf(z3, Ws[(jb * 4 + 3) * DIMC + lane], outacc);
    }
    float o = tanhf(outacc + b[lane]);
    if (layer == 2) {
        g_x2[node * DIMC + lane] = o;
    } else {
        g_x3[node * DIMC + lane] = o;
        float t = acc.x * W4[sub * 4 + 0] + acc.y * W4[sub * 4 + 1]
                + acc.z * W4[sub * 4 + 2] + acc.w * W4[sub * 4 + 3];
        t += __shfl_xor_sync(0xffffffffu, t, 1);
        t += __shfl_xor_sync(0xffffffffu, t, 2);
        t += __shfl_xor_sync(0xffffffffu, t, 4);
        if (lane == 0) g_score[node] = tanhf(t + b4[0]);
    }
}

// ---------------- sort pooling: per-graph bitonic-512, top-100 ----------------
__global__ void k_sortpool() {
    __shared__ float s[512];
    __shared__ int   si[512];
    int g = blockIdx.x, tid = threadIdx.x;  // 256 threads
    for (int i = tid; i < 512; i += 256) {
        if (i < NPER) { s[i] = g_score[g * NPER + i]; si[i] = i; }
        else          { s[i] = __int_as_float(0xff800000); si[i] = 0x7FFFFFFF; }
    }
    __syncthreads();
    for (int k = 2; k <= 512; k <<= 1) {
        for (int j = k >> 1; j > 0; j >>= 1) {
            for (int i = tid; i < 512; i += 256) {
                int ixj = i ^ j;
                if (ixj > i) {
                    float a = s[i], bb = s[ixj];
                    int ia = si[i], ib = si[ixj];
                    bool before = (a > bb) || (a == bb && ia < ib);
                    bool dirDesc = ((i & k) == 0);
                    if (dirDesc ? !before : before) {
                        s[i] = bb; s[ixj] = a; si[i] = ib; si[ixj] = ia;
                    }
                }
            }
            __syncthreads();
        }
    }
    if (tid < KTOP) g_topk[g * KTOP + tid] = g * NPER + si[tid];
}

// ---------------- conv1 + relu + maxpool(2,2), 4 channels/thread ----------------
__global__ void k_conv1pool(const float* __restrict__ cw1, const float* __restrict__ cb1) {
    __shared__ float xs[KTOP * TOTALC];
    int g = blockIdx.x, tid = threadIdx.x;  // 256 threads
    for (int i = tid; i < KTOP * TOTALC; i += 256) {
        int kslot = i / TOTALC, t = i - kslot * TOTALC;
        int n = g_topk[g * KTOP + kslot];
        float v;
        if (t < 32)      v = g_x1[n * DIMC + t];
        else if (t < 64) v = g_x2[n * DIMC + t - 32];
        else if (t < 96) v = g_x3[n * DIMC + t - 64];
        else             v = g_score[n];
        xs[i] = v;
    }
    __syncthreads();
    for (int item = tid; item < 32 * 50; item += 256) {
        int cb = item / 50, j = item - cb * 50;
        const float* r0 = xs + (2 * j) * TOTALC;
        const float* r1 = r0 + TOTALC;
        float a[8];
#pragma unroll
        for (int q = 0; q < 4; q++) { float bb = cb1[cb + q * 32]; a[q] = bb; a[4 + q] = bb; }
#pragma unroll 2
        for (int t = 0; t < TOTALC; t++) {
            float v0 = r0[t], v1 = r1[t];
#pragma unroll
            for (int q = 0; q < 4; q++) {
                float wv = cw1[(cb + q * 32) * TOTALC + t];
                a[q]     = fmaf(v0, wv, a[q]);
                a[4 + q] = fmaf(v1, wv, a[4 + q]);
            }
        }
#pragma unroll
        for (int q = 0; q < 4; q++)
            g_p1[(g * 128 + cb + q * 32) * 50 + j] = fmaxf(fmaxf(a[q], a[4 + q]), 0.0f);
    }
}

// ---------------- conv2 (128->64, k=5) + relu, 4 channels/thread ----------------
__global__ void k_conv2(const float* __restrict__ cw2, const float* __restrict__ cb2) {
    __shared__ float ps[128 * 50];
    int g = blockIdx.x, tid = threadIdx.x;  // 256 threads
    for (int i = tid; i < 128 * 50; i += 256) ps[i] = g_p1[g * 6400 + i];
    __syncthreads();
    for (int item = tid; item < 16 * 46; item += 256) {
        int ob = item / 46, j = item - ob * 46;
        float a0 = cb2[ob], a1 = cb2[ob + 16], a2 = cb2[ob + 32], a3 = cb2[ob + 48];
        const float* w0 = cw2 + (ob)      * 640;
        const float* w1 = cw2 + (ob + 16) * 640;
        const float* w2 = cw2 + (ob + 32) * 640;
        const float* w3 = cw2 + (ob + 48) * 640;
#pragma unroll 2
        for (int i = 0; i < 128; i++) {
            const float* pr = ps + i * 50 + j;
            float p0 = pr[0], p1 = pr[1], p2 = pr[2], p3 = pr[3], p4 = pr[4];
            const float* q0 = w0 + i * 5;
            const float* q1 = w1 + i * 5;
            const float* q2 = w2 + i * 5;
            const float* q3 = w3 + i * 5;
            a0 = fmaf(p0, q0[0], a0); a0 = fmaf(p1, q0[1], a0); a0 = fmaf(p2, q0[2], a0);
            a0 = fmaf(p3, q0[3], a0); a0 = fmaf(p4, q0[4], a0);
            a1 = fmaf(p0, q1[0], a1); a1 = fmaf(p1, q1[1], a1); a1 = fmaf(p2, q1[2], a1);
            a1 = fmaf(p3, q1[3], a1); a1 = fmaf(p4, q1[4], a1);
            a2 = fmaf(p0, q2[0], a2); a2 = fmaf(p1, q2[1], a2); a2 = fmaf(p2, q2[2], a2);
            a2 = fmaf(p3, q2[3], a2); a2 = fmaf(p4, q2[4], a2);
            a3 = fmaf(p0, q3[0], a3); a3 = fmaf(p1, q3[1], a3); a3 = fmaf(p2, q3[2], a3);
            a3 = fmaf(p3, q3[3], a3); a3 = fmaf(p4, q3[4], a3);
        }
        g_c2f[g * 2944 + (ob)      * 46 + j] = fmaxf(a0, 0.0f);
        g_c2f[g * 2944 + (ob + 16) * 46 + j] = fmaxf(a1, 0.0f);
        g_c2f[g * 2944 + (ob + 32) * 46 + j] = fmaxf(a2, 0.0f);
        g_c2f[g * 2944 + (ob + 48) * 46 + j] = fmaxf(a3, 0.0f);
    }
}

// ---------------- fc1 + relu (4 graphs per block) ----------------
__global__ void k_fc1(const float* __restrict__ fw1, const float* __restrict__ fb1) {
    __shared__ float cs[4 * 2944];
    int gb = blockIdx.x, tid = threadIdx.x;  // 128 threads
    int g0 = gb * 4;
    for (int i = tid; i < 4 * 2944; i += 128) {
        int g = g0 + i / 2944;
        cs[i] = (g < NGRAPH) ? g_c2f[g * 2944 + (i % 2944)] : 0.0f;
    }
    __syncthreads();
    const float4* wr = reinterpret_cast<const float4*>(fw1 + (size_t)tid * 2944);
    const float4* c0 = reinterpret_cast<const float4*>(cs);
    const float4* c1 = reinterpret_cast<const float4*>(cs + 2944);
    const float4* c2 = reinterpret_cast<const float4*>(cs + 2 * 2944);
    const float4* c3 = reinterpret_cast<const float4*>(cs + 3 * 2944);
    float a0 = 0, a1 = 0, a2 = 0, a3 = 0;
    for (int d = 0; d < 736; d++) {
        float4 w = wr[d];
        float4 v;
        v = c0[d]; a0 += w.x * v.x + w.y * v.y + w.z * v.z + w.w * v.w;
        v = c1[d]; a1 += w.x * v.x + w.y * v.y + w.z * v.z + w.w * v.w;
        v = c2[d]; a2 += w.x * v.x + w.y * v.y + w.z * v.z + w.w * v.w;
        v = c3[d]; a3 += w.x * v.x + w.y * v.y + w.z * v.z + w.w * v.w;
    }
    float bb = fb1[tid];
    if (g0 + 0 < NGRAPH) g_hfc[(g0 + 0) * 128 + tid] = fmaxf(a0 + bb, 0.0f);
    if (g0 + 1 < NGRAPH) g_hfc[(g0 + 1) * 128 + tid] = fmaxf(a1 + bb, 0.0f);
    if (g0 + 2 < NGRAPH) g_hfc[(g0 + 2) * 128 + tid] = fmaxf(a2 + bb, 0.0f);
    if (g0 + 3 < NGRAPH) g_hfc[(g0 + 3) * 128 + tid] = fmaxf(a3 + bb, 0.0f);
}

// ---------------- fc3 + log_softmax ----------------
__global__ void k_fc3(const float* __restrict__ fw3, const float* __restrict__ fb3,
                      float* __restrict__ out) {
    int b = blockIdx.x * 256 + threadIdx.x;
    if (b >= NGRAPH) return;
    float l0 = fb3[0], l1 = fb3[1];
#pragma unroll 4
    for (int d = 0; d < 128; d++) {
        float h = g_hfc[b * 128 + d];
        l0 = fmaf(h, fw3[d], l0);
        l1 = fmaf(h, fw3[128 + d], l1);
    }
    float m = fmaxf(l0, l1);
    float lse = m + logf(expf(l0 - m) + expf(l1 - m));
    out[b * 2 + 0] = l0 - lse;
    out[b * 2 + 1] = l1 - lse;
}

// ---------------- launch ----------------
extern "C" void kernel_launch(void* const* d_in, const int* in_sizes, int n_in,
                              void* d_out, int out_size) {
    const float* x   = (const float*)d_in[0];
    const int*   ei  = (const int*)d_in[1];
    const int*   src = ei;
    const int*   dst = ei + N_EDGES;
    const float* W1 = (const float*)d_in[3];  const float* b1 = (const float*)d_in[4];
    const float* W2 = (const float*)d_in[5];  const float* b2 = (const float*)d_in[6];
    const float* W3 = (const float*)d_in[7];  const float* b3 = (const float*)d_in[8];
    const float* W4 = (const float*)d_in[9];  const float* b4 = (const float*)d_in[10];
    const float* cw1 = (const float*)d_in[11]; const float* cb1 = (const float*)d_in[12];
    const float* cw2 = (const float*)d_in[13]; const float* cb2 = (const float*)d_in[14];
    const float* fw1 = (const float*)d_in[15]; const float* fb1 = (const float*)d_in[16];
    const float* fw3 = (const float*)d_in[17]; const float* fb3 = (const float*)d_in[18];
    float* out = (float*)d_out;

    const int TB = 256;
    const int gN  = (N_NODES + TB - 1) / TB;     // 391
    const int gE  = (N_EDGES + TB - 1) / TB;     // 12500
    const int gG8 = (N_NODES + 7) / 8;           // 12500

    k_hist_init<<<gN, TB>>>();                       // 0
    k_hist<<<gE, TB>>>(dst);                         // 1
    k_scanA<<<NBLK_SCAN, SCAN_BLK>>>();              // 2
    k_gemm1<<<N_NODES / GM_NODES, TB>>>(x, W1);      // 3  <- profiled
    k_scanB<<<1, 128>>>();                           // 4
    k_scanC<<<gN, TB>>>();                           // 5
    k_fill<<<gE, TB>>>(src, dst);                    // 6

    k_gather<<<gG8, TB>>>(1, nullptr, b1, nullptr, nullptr);
    k_gather<<<gG8, TB>>>(2, W2, b2, nullptr, nullptr);
    k_gather<<<gG8, TB>>>(3, W3, b3, W4, b4);

    k_sortpool<<<NGRAPH, TB>>>();
    k_conv1pool<<<NGRAPH, TB>>>(cw1, cb1);
    k_conv2<<<NGRAPH, TB>>>(cw2, cb2);
    k_fc1<<<(NGRAPH + 3) / 4, 128>>>(fw1, fb1);
    k_fc3<<<1, TB>>>(fw3, fb3, out);
}

// round 6
// speedup vs baseline: 1.6604x; 1.0293x over previous
#include <cuda_runtime.h>
#include <math.h>

#define N_NODES 100000
#define N_EDGES 3200000
#define DIMC 32
#define INDIM 128
#define NGRAPH 250
#define NPER 400
#define KTOP 100
#define TOTALC 97
#define SCAN_BLK 1024
#define NBLK_SCAN ((N_NODES + SCAN_BLK - 1) / SCAN_BLK)   // 98
#define GM_NODES 32

// ---------------- device scratch ----------------
__device__ int   g_cnt[N_NODES];
__device__ int   g_fill[N_NODES];
__device__ int   g_off[N_NODES + 1];
__device__ int   g_bsum[NBLK_SCAN];
__device__ int   g_sync1, g_sync2;
__device__ float g_dis[N_NODES];
__device__ float g_deginv[N_NODES];
__device__ int2  g_csr[N_EDGES];          // {src, coef bits}
__device__ float g_h[N_NODES * DIMC];
__device__ float g_x1[N_NODES * DIMC];
__device__ float g_x2[N_NODES * DIMC];
__device__ float g_x3[N_NODES * DIMC];
__device__ float g_score[N_NODES];
__device__ int   g_topk[NGRAPH * KTOP];
__device__ float g_p1[NGRAPH * 128 * 50];
__device__ float g_c2f[NGRAPH * 2944];
__device__ float g_hfc[NGRAPH * 128];

// ---------------- h = X @ W1 (128 -> 32), tiled GEMM; also zeroes g_cnt/syncs ----------------
__global__ void k_gemm1(const float* __restrict__ X, const float* __restrict__ W) {
    __shared__ float Xs[GM_NODES * INDIM];   // 16 KB
    __shared__ float Ws[INDIM * DIMC];       // 16 KB
    int tid = threadIdx.x;
    int nbase = blockIdx.x * GM_NODES;       // 3125 blocks, exact

    // housekeeping for this replay: zero histogram + barrier counters
    int gt = blockIdx.x * 256 + tid;
    if (gt < N_NODES) g_cnt[gt] = 0;
    if (gt == 0) { g_sync1 = 0; g_sync2 = 0; }

    const float4* Wg = reinterpret_cast<const float4*>(W);
    float4* Ws4 = reinterpret_cast<float4*>(Ws);
    for (int i = tid; i < INDIM * DIMC / 4; i += 256) Ws4[i] = Wg[i];
    const float4* Xg = reinterpret_cast<const float4*>(X + (size_t)nbase * INDIM);
    float4* Xs4 = reinterpret_cast<float4*>(Xs);
    for (int i = tid; i < GM_NODES * INDIM / 4; i += 256) Xs4[i] = Xg[i];
    __syncthreads();

    int dim = tid & 31, nq = tid >> 5;
    const float* xr0 = Xs + (nq * 4 + 0) * INDIM;
    const float* xr1 = Xs + (nq * 4 + 1) * INDIM;
    const float* xr2 = Xs + (nq * 4 + 2) * INDIM;
    const float* xr3 = Xs + (nq * 4 + 3) * INDIM;
    float a0 = 0.f, a1 = 0.f, a2 = 0.f, a3 = 0.f;
#pragma unroll 4
    for (int kb = 0; kb < INDIM; kb += 4) {
        float w0 = Ws[(kb + 0) * DIMC + dim];
        float w1 = Ws[(kb + 1) * DIMC + dim];
        float w2 = Ws[(kb + 2) * DIMC + dim];
        float w3 = Ws[(kb + 3) * DIMC + dim];
        float4 v0 = *reinterpret_cast<const float4*>(xr0 + kb);
        float4 v1 = *reinterpret_cast<const float4*>(xr1 + kb);
        float4 v2 = *reinterpret_cast<const float4*>(xr2 + kb);
        float4 v3 = *reinterpret_cast<const float4*>(xr3 + kb);
        a0 = fmaf(v0.x, w0, a0); a0 = fmaf(v0.y, w1, a0);
        a0 = fmaf(v0.z, w2, a0); a0 = fmaf(v0.w, w3, a0);
        a1 = fmaf(v1.x, w0, a1); a1 = fmaf(v1.y, w1, a1);
        a1 = fmaf(v1.z, w2, a1); a1 = fmaf(v1.w, w3, a1);
        a2 = fmaf(v2.x, w0, a2); a2 = fmaf(v2.y, w1, a2);
        a2 = fmaf(v2.z, w2, a2); a2 = fmaf(v2.w, w3, a2);
        a3 = fmaf(v3.x, w0, a3); a3 = fmaf(v3.y, w1, a3);
        a3 = fmaf(v3.z, w2, a3); a3 = fmaf(v3.w, w3, a3);
    }
    int nb = nbase + nq * 4;
    g_h[(nb + 0) * DIMC + dim] = a0;
    g_h[(nb + 1) * DIMC + dim] = a1;
    g_h[(nb + 2) * DIMC + dim] = a2;
    g_h[(nb + 3) * DIMC + dim] = a3;
}

// ---------------- degree histogram (int4, 4 edges/thread) ----------------
__global__ void k_hist(const int* __restrict__ dst) {
    int e4 = blockIdx.x * 256 + threadIdx.x;
    if (e4 < N_EDGES / 4) {
        int4 d = reinterpret_cast<const int4*>(dst)[e4];
        atomicAdd(&g_cnt[d.x], 1);
        atomicAdd(&g_cnt[d.y], 1);
        atomicAdd(&g_cnt[d.z], 1);
        atomicAdd(&g_cnt[d.w], 1);
    }
}

// ---------------- fused scan + degree-norm + CSR fill (98 resident blocks) ----------------
__global__ void __launch_bounds__(SCAN_BLK, 1) k_scanfill(const int* __restrict__ src,
                                                          const int* __restrict__ dst) {
    __shared__ int s[SCAN_BLK];
    __shared__ int sprefix;
    int tid = threadIdx.x;
    int b = blockIdx.x;
    int i = b * SCAN_BLK + tid;
    int v = (i < N_NODES) ? g_cnt[i] : 0;
    s[tid] = v;
    __syncthreads();
    for (int o = 1; o < SCAN_BLK; o <<= 1) {
        int t = (tid >= o) ? s[tid - o] : 0;
        __syncthreads();
        s[tid] += t;                      // inclusive scan
        __syncthreads();
    }
    if (tid == SCAN_BLK - 1) g_bsum[b] = s[tid];
    // device-wide barrier 1 (all 98 blocks resident)
    if (tid == 0) {
        __threadfence();
        atomicAdd(&g_sync1, 1);
        while (atomicAdd(&g_sync1, 0) < NBLK_SCAN) __nanosleep(64);
    }
    __syncthreads();
    if (tid == 0) {
        int run = 0;
        for (int q = 0; q < b; q++) run += g_bsum[q];
        sprefix = run;
    }
    __syncthreads();
    if (i < N_NODES) {
        g_off[i] = sprefix + s[tid] - v;  // global exclusive
        g_fill[i] = 0;
        float d = (float)v + 1.0f;
        g_dis[i] = rsqrtf(d);
        g_deginv[i] = 1.0f / d;
    }
    if (i == N_NODES - 1) g_off[N_NODES] = N_EDGES;
    // device-wide barrier 2
    if (tid == 0) {
        __threadfence();
        atomicAdd(&g_sync2, 1);
        while (atomicAdd(&g_sync2, 0) < NBLK_SCAN) __nanosleep(64);
    }
    __syncthreads();
    // CSR fill, grid-stride
    const int stride = NBLK_SCAN * SCAN_BLK;
    for (int e = b * SCAN_BLK + tid; e < N_EDGES; e += stride) {
        int ss = src[e], dd = dst[e];
        int pos = g_off[dd] + atomicAdd(&g_fill[dd], 1);
        float c = g_dis[ss] * g_dis[dd];
        g_csr[pos] = make_int2(ss, __float_as_int(c));
    }
}

// ---------------- CSR gather (16 edges/warp-iter, float4) + fused transform ----------------
__global__ void __launch_bounds__(256) k_gather(int layer, const float* __restrict__ W,
                         const float* __restrict__ b,
                         const float* __restrict__ W4, const float* __restrict__ b4) {
    __shared__ float Ws[DIMC * DIMC];
    int tid = threadIdx.x;
    if (layer >= 2) {
        for (int i = tid; i < DIMC * DIMC; i += 256) Ws[i] = W[i];
        __syncthreads();
    }
    const float* __restrict__ X = (layer == 1) ? g_h : (layer == 2 ? g_x1 : g_x2);
    int node = blockIdx.x * 8 + (tid >> 5);
    if (node >= N_NODES) return;
    int lane = tid & 31;
    int grp = lane >> 3, sub = lane & 7;
    int beg = g_off[node], end = g_off[node + 1];

    float4 acc = make_float4(0.f, 0.f, 0.f, 0.f);
    for (int base = beg; base < end; base += 16) {
        int e0 = base + grp, e1 = e0 + 4, e2 = e0 + 8, e3 = e0 + 12;
        int s0 = 0, s1 = 0, s2 = 0, s3 = 0;
        float c0 = 0.f, c1 = 0.f, c2 = 0.f, c3 = 0.f;
        if (e0 < end) { int2 t = g_csr[e0]; s0 = t.x; c0 = __int_as_float(t.y); }
        if (e1 < end) { int2 t = g_csr[e1]; s1 = t.x; c1 = __int_as_float(t.y); }
        if (e2 < end) { int2 t = g_csr[e2]; s2 = t.x; c2 = __int_as_float(t.y); }
        if (e3 < end) { int2 t = g_csr[e3]; s3 = t.x; c3 = __int_as_float(t.y); }
        const float4 v0 = *reinterpret_cast<const float4*>(&X[s0 * DIMC + sub * 4]);
        const float4 v1 = *reinterpret_cast<const float4*>(&X[s1 * DIMC + sub * 4]);
        const float4 v2 = *reinterpret_cast<const float4*>(&X[s2 * DIMC + sub * 4]);
        const float4 v3 = *reinterpret_cast<const float4*>(&X[s3 * DIMC + sub * 4]);
        acc.x = fmaf(c0, v0.x, fmaf(c1, v1.x, fmaf(c2, v2.x, fmaf(c3, v3.x, acc.x))));
        acc.y = fmaf(c0, v0.y, fmaf(c1, v1.y, fmaf(c2, v2.y, fmaf(c3, v3.y, acc.y))));
        acc.z = fmaf(c0, v0.z, fmaf(c1, v1.z, fmaf(c2, v2.z, fmaf(c3, v3.z, acc.z))));
        acc.w = fmaf(c0, v0.w, fmaf(c1, v1.w, fmaf(c2, v2.w, fmaf(c3, v3.w, acc.w))));
    }
#pragma unroll
    for (int off = 8; off <= 16; off <<= 1) {
        acc.x += __shfl_xor_sync(0xffffffffu, acc.x, off);
        acc.y += __shfl_xor_sync(0xffffffffu, acc.y, off);
        acc.z += __shfl_xor_sync(0xffffffffu, acc.z, off);
        acc.w += __shfl_xor_sync(0xffffffffu, acc.w, off);
    }
    float dinv = g_deginv[node];
    const float4 xself = *reinterpret_cast<const float4*>(&X[node * DIMC + sub * 4]);
    acc.x = fmaf(xself.x, dinv, acc.x);
    acc.y = fmaf(xself.y, dinv, acc.y);
    acc.z = fmaf(xself.z, dinv, acc.z);
    acc.w = fmaf(xself.w, dinv, acc.w);

    if (layer == 1) {
        if (grp == 0) {
            float4 o;
            o.x = tanhf(acc.x + b[sub * 4 + 0]);
            o.y = tanhf(acc.y + b[sub * 4 + 1]);
            o.z = tanhf(acc.z + b[sub * 4 + 2]);
            o.w = tanhf(acc.w + b[sub * 4 + 3]);
            *reinterpret_cast<float4*>(&g_x1[node * DIMC + sub * 4]) = o;
        }
        return;
    }

    float outacc = 0.0f;
#pragma unroll
    for (int jb = 0; jb < 8; jb++) {
        float z0 = __shfl_sync(0xffffffffu, acc.x, jb);
        float z1 = __shfl_sync(0xffffffffu, acc.y, jb);
        float z2 = __shfl_sync(0xffffffffu, acc.z, jb);
        float z3 = __shfl_sync(0xffffffffu, acc.w, jb);
        outacc = fmaf(z0, Ws[(jb * 4 + 0) * DIMC + lane], outacc);
        outacc = fmaf(z1, Ws[(jb * 4 + 1) * DIMC + lane], outacc);
        outacc = fmaf(z2, Ws[(jb * 4 + 2) * DIMC + lane], outacc);
        outacc = fmaf(z3, Ws[(jb * 4 + 3) * DIMC + lane], outacc);
    }
    float o = tanhf(outacc + b[lane]);
    if (layer == 2) {
        g_x2[node * DIMC + lane] = o;
    } else {
        g_x3[node * DIMC + lane] = o;
        float t = acc.x * W4[sub * 4 + 0] + acc.y * W4[sub * 4 + 1]
                + acc.z * W4[sub * 4 + 2] + acc.w * W4[sub * 4 + 3];
        t += __shfl_xor_sync(0xffffffffu, t, 1);
        t += __shfl_xor_sync(0xffffffffu, t, 2);
        t += __shfl_xor_sync(0xffffffffu, t, 4);
        if (lane == 0) g_score[node] = tanhf(t + b4[0]);
    }
}

// ---------------- sort pooling: per-graph bitonic-512, top-100 ----------------
__global__ void k_sortpool() {
    __shared__ float s[512];
    __shared__ int   si[512];
    int g = blockIdx.x, tid = threadIdx.x;  // 256 threads
    for (int i = tid; i < 512; i += 256) {
        if (i < NPER) { s[i] = g_score[g * NPER + i]; si[i] = i; }
        else          { s[i] = __int_as_float(0xff800000); si[i] = 0x7FFFFFFF; }
    }
    __syncthreads();
    for (int k = 2; k <= 512; k <<= 1) {
        for (int j = k >> 1; j > 0; j >>= 1) {
            for (int i = tid; i < 512; i += 256) {
                int ixj = i ^ j;
                if (ixj > i) {
                    float a = s[i], bb = s[ixj];
                    int ia = si[i], ib = si[ixj];
                    bool before = (a > bb) || (a == bb && ia < ib);
                    bool dirDesc = ((i & k) == 0);
                    if (dirDesc ? !before : before) {
                        s[i] = bb; s[ixj] = a; si[i] = ib; si[ixj] = ia;
                    }
                }
            }
            __syncthreads();
        }
    }
    if (tid < KTOP) g_topk[g * KTOP + tid] = g * NPER + si[tid];
}

// ---------------- conv1 + relu + maxpool(2,2), 4 channels/thread ----------------
__global__ void k_conv1pool(const float* __restrict__ cw1, const float* __restrict__ cb1) {
    __shared__ float xs[KTOP * TOTALC];
    int g = blockIdx.x, tid = threadIdx.x;  // 256 threads
    for (int i = tid; i < KTOP * TOTALC; i += 256) {
        int kslot = i / TOTALC, t = i - kslot * TOTALC;
        int n = g_topk[g * KTOP + kslot];
        float v;
        if (t < 32)      v = g_x1[n * DIMC + t];
        else if (t < 64) v = g_x2[n * DIMC + t - 32];
        else if (t < 96) v = g_x3[n * DIMC + t - 64];
        else             v = g_score[n];
        xs[i] = v;
    }
    __syncthreads();
    for (int item = tid; item < 32 * 50; item += 256) {
        int cb = item / 50, j = item - cb * 50;
        const float* r0 = xs + (2 * j) * TOTALC;
        const float* r1 = r0 + TOTALC;
        float a[8];
#pragma unroll
        for (int q = 0; q < 4; q++) { float bb = cb1[cb + q * 32]; a[q] = bb; a[4 + q] = bb; }
#pragma unroll 2
        for (int t = 0; t < TOTALC; t++) {
            float v0 = r0[t], v1 = r1[t];
#pragma unroll
            for (int q = 0; q < 4; q++) {
                float wv = cw1[(cb + q * 32) * TOTALC + t];
                a[q]     = fmaf(v0, wv, a[q]);
                a[4 + q] = fmaf(v1, wv, a[4 + q]);
            }
        }
#pragma unroll
        for (int q = 0; q < 4; q++)
            g_p1[(g * 128 + cb + q * 32) * 50 + j] = fmaxf(fmaxf(a[q], a[4 + q]), 0.0f);
    }
}

// ---------------- conv2 (128->64, k=5) + relu, 4 channels/thread ----------------
__global__ void k_conv2(const float* __restrict__ cw2, const float* __restrict__ cb2) {
    __shared__ float ps[128 * 50];
    int g = blockIdx.x, tid = threadIdx.x;  // 256 threads
    for (int i = tid; i < 128 * 50; i += 256) ps[i] = g_p1[g * 6400 + i];
    __syncthreads();
    for (int item = tid; item < 16 * 46; item += 256) {
        int ob = item / 46, j = item - ob * 46;
        float a0 = cb2[ob], a1 = cb2[ob + 16], a2 = cb2[ob + 32], a3 = cb2[ob + 48];
        const float* w0 = cw2 + (ob)      * 640;
        const float* w1 = cw2 + (ob + 16) * 640;
        const float* w2 = cw2 + (ob + 32) * 640;
        const float* w3 = cw2 + (ob + 48) * 640;
#pragma unroll 2
        for (int i = 0; i < 128; i++) {
            const float* pr = ps + i * 50 + j;
            float p0 = pr[0], p1 = pr[1], p2 = pr[2], p3 = pr[3], p4 = pr[4];
            const float* q0 = w0 + i * 5;
            const float* q1 = w1 + i * 5;
            const float* q2 = w2 + i * 5;
            const float* q3 = w3 + i * 5;
            a0 = fmaf(p0, q0[0], a0); a0 = fmaf(p1, q0[1], a0); a0 = fmaf(p2, q0[2], a0);
            a0 = fmaf(p3, q0[3], a0); a0 = fmaf(p4, q0[4], a0);
            a1 = fmaf(p0, q1[0], a1); a1 = fmaf(p1, q1[1], a1); a1 = fmaf(p2, q1[2], a1);
            a1 = fmaf(p3, q1[3], a1); a1 = fmaf(p4, q1[4], a1);
            a2 = fmaf(p0, q2[0], a2); a2 = fmaf(p1, q2[1], a2); a2 = fmaf(p2, q2[2], a2);
            a2 = fmaf(p3, q2[3], a2); a2 = fmaf(p4, q2[4], a2);
            a3 = fmaf(p0, q3[0], a3); a3 = fmaf(p1, q3[1], a3); a3 = fmaf(p2, q3[2], a3);
            a3 = fmaf(p3, q3[3], a3); a3 = fmaf(p4, q3[4], a3);
        }
        g_c2f[g * 2944 + (ob)      * 46 + j] = fmaxf(a0, 0.0f);
        g_c2f[g * 2944 + (ob + 16) * 46 + j] = fmaxf(a1, 0.0f);
        g_c2f[g * 2944 + (ob + 32) * 46 + j] = fmaxf(a2, 0.0f);
        g_c2f[g * 2944 + (ob + 48) * 46 + j] = fmaxf(a3, 0.0f);
    }
}

// ---------------- fc1 + relu (4 graphs per block, 2-way k-split, 256 thr) ----------------
__global__ void k_fc1(const float* __restrict__ fw1, const float* __restrict__ fb1) {
    __shared__ float cs[4 * 2944];        // 47.1 KB
    __shared__ float part[256];
    int gb = blockIdx.x, tid = threadIdx.x;  // 256 threads
    int g0 = gb * 4;
    for (int i = tid; i < 4 * 2944; i += 256) {
        int g = g0 + i / 2944;
        cs[i] = (g < NGRAPH) ? g_c2f[g * 2944 + (i % 2944)] : 0.0f;
    }
    __syncthreads();
    int half = tid >> 7;                  // 0 or 1
    int o    = tid & 127;                 // output index
    int dbeg = half * 368;                // half of 736 float4 groups
    const float4* wr = reinterpret_cast<const float4*>(fw1 + (size_t)o * 2944) + dbeg;
    const float4* c0 = reinterpret_cast<const float4*>(cs) + dbeg;
    const float4* c1 = reinterpret_cast<const float4*>(cs + 2944) + dbeg;
    const float4* c2 = reinterpret_cast<const float4*>(cs + 2 * 2944) + dbeg;
    const float4* c3 = reinterpret_cast<const float4*>(cs + 3 * 2944) + dbeg;
    float a0 = 0, a1 = 0, a2 = 0, a3 = 0;
    for (int d = 0; d < 368; d++) {
        float4 w = wr[d];
        float4 v;
        v = c0[d]; a0 += w.x * v.x + w.y * v.y + w.z * v.z + w.w * v.w;
        v = c1[d]; a1 += w.x * v.x + w.y * v.y + w.z * v.z + w.w * v.w;
        v = c2[d]; a2 += w.x * v.x + w.y * v.y + w.z * v.z + w.w * v.w;
        v = c3[d]; a3 += w.x * v.x + w.y * v.y + w.z * v.z + w.w * v.w;
    }
    // stash high-half partials, combine in low half
    if (half == 1) { part[o] = a0; part[o + 128] = a1; }
    __syncthreads();
    if (half == 0) {
        a0 += part[o]; a1 += part[o + 128];
    }
    __syncthreads();
    if (half == 1) { part[o] = a2; part[o + 128] = a3; }
    __syncthreads();
    if (half == 0) {
        a2 += part[o]; a3 += part[o + 128];
        float bb = fb1[o];
        if (g0 + 0 < NGRAPH) g_hfc[(g0 + 0) * 128 + o] = fmaxf(a0 + bb, 0.0f);
        if (g0 + 1 < NGRAPH) g_hfc[(g0 + 1) * 128 + o] = fmaxf(a1 + bb, 0.0f);
        if (g0 + 2 < NGRAPH) g_hfc[(g0 + 2) * 128 + o] = fmaxf(a2 + bb, 0.0f);
        if (g0 + 3 < NGRAPH) g_hfc[(g0 + 3) * 128 + o] = fmaxf(a3 + bb, 0.0f);
    }
}

// ---------------- fc3 + log_softmax ----------------
__global__ void k_fc3(const float* __restrict__ fw3, const float* __restrict__ fb3,
                      float* __restrict__ out) {
    int b = blockIdx.x * 256 + threadIdx.x;
    if (b >= NGRAPH) return;
    float l0 = fb3[0], l1 = fb3[1];
#pragma unroll 4
    for (int d = 0; d < 128; d++) {
        float h = g_hfc[b * 128 + d];
        l0 = fmaf(h, fw3[d], l0);
        l1 = fmaf(h, fw3[128 + d], l1);
    }
    float m = fmaxf(l0, l1);
    float lse = m + logf(expf(l0 - m) + expf(l1 - m));
    out[b * 2 + 0] = l0 - lse;
    out[b * 2 + 1] = l1 - lse;
}

// ---------------- launch ----------------
extern "C" void kernel_launch(void* const* d_in, const int* in_sizes, int n_in,
                              void* d_out, int out_size) {
    const float* x   = (const float*)d_in[0];
    const int*   ei  = (const int*)d_in[1];
    const int*   src = ei;
    const int*   dst = ei + N_EDGES;
    const float* W1 = (const float*)d_in[3];  const float* b1 = (const float*)d_in[4];
    const float* W2 = (const float*)d_in[5];  const float* b2 = (const float*)d_in[6];
    const float* W3 = (const float*)d_in[7];  const float* b3 = (const float*)d_in[8];
    const float* W4 = (const float*)d_in[9];  const float* b4 = (const float*)d_in[10];
    const float* cw1 = (const float*)d_in[11]; const float* cb1 = (const float*)d_in[12];
    const float* cw2 = (const float*)d_in[13]; const float* cb2 = (const float*)d_in[14];
    const float* fw1 = (const float*)d_in[15]; const float* fb1 = (const float*)d_in[16];
    const float* fw3 = (const float*)d_in[17]; const float* fb3 = (const float*)d_in[18];
    float* out = (float*)d_out;

    const int TB = 256;
    const int gG8 = (N_NODES + 7) / 8;           // 12500

    k_gemm1<<<N_NODES / GM_NODES, TB>>>(x, W1);      // 0 (also zeroes g_cnt + syncs)
    k_hist<<<N_EDGES / 4 / TB, TB>>>(dst);           // 1
    k_scanfill<<<NBLK_SCAN, SCAN_BLK>>>(src, dst);   // 2
    k_gather<<<gG8, TB>>>(1, nullptr, b1, nullptr, nullptr);  // 3 <- profiled
    k_gather<<<gG8, TB>>>(2, W2, b2, nullptr, nullptr);       // 4
    k_gather<<<gG8, TB>>>(3, W3, b3, W4, b4);                 // 5

    k_sortpool<<<NGRAPH, TB>>>();                    // 6
    k_conv1pool<<<NGRAPH, TB>>>(cw1, cb1);           // 7
    k_conv2<<<NGRAPH, TB>>>(cw2, cb2);               // 8
    k_fc1<<<(NGRAPH + 3) / 4, TB>>>(fw1, fb1);       // 9
    k_fc3<<<1, TB>>>(fw3, fb3, out);                 // 10
}

// round 7
// speedup vs baseline: 1.8387x; 1.1074x over previous
#include <cuda_runtime.h>
#include <math.h>

#define N_NODES 100000
#define N_EDGES 3200000
#define DIMC 32
#define INDIM 128
#define NGRAPH 250
#define NPER 400
#define KTOP 100
#define TOTALC 97
#define SCAN_BLK 1024
#define NBLK_SCAN ((N_NODES + SCAN_BLK - 1) / SCAN_BLK)   // 98
#define GM_NODES 32

// ---------------- device scratch ----------------
__device__ int   g_cnt[N_NODES];
__device__ int   g_fill[N_NODES];       // working offsets during fill
__device__ int   g_off[N_NODES + 1];
__device__ int   g_bsum[NBLK_SCAN];
__device__ int   g_syncc;               // monotonic barrier counter (reset by k_gemm1)
__device__ float g_dis[N_NODES];
__device__ int   g_csr[N_EDGES];        // src * 32 (pre-shifted row offset)
__device__ float g_y0[N_NODES * DIMC];  // dis * (X@W1)
__device__ float g_x1[N_NODES * DIMC];
__device__ float g_y1[N_NODES * DIMC];
__device__ float g_x2[N_NODES * DIMC];
__device__ float g_y2[N_NODES * DIMC];
__device__ float g_x3[N_NODES * DIMC];
__device__ float g_score[N_NODES];
__device__ float g_c2f[NGRAPH * 2944];

// ---------------- fused CSR build: zero -> hist -> scan -> fill ----------------
__device__ __forceinline__ void grid_barrier(int target) {
    if (threadIdx.x == 0) {
        __threadfence();
        atomicAdd(&g_syncc, 1);
        while (atomicAdd(&g_syncc, 0) < target) __nanosleep(32);
    }
    __syncthreads();
}

__global__ void __launch_bounds__(SCAN_BLK, 1) k_scanfill(const int* __restrict__ src,
                                                          const int* __restrict__ dst) {
    __shared__ int s[SCAN_BLK];
    __shared__ int sprefix;
    int tid = threadIdx.x;
    int b = blockIdx.x;
    int gid = b * SCAN_BLK + tid;
    const int NT = NBLK_SCAN * SCAN_BLK;   // 100352

    // phase 0: zero histogram
    if (gid < N_NODES) g_cnt[gid] = 0;
    if (gid == 0) g_off[N_NODES] = N_EDGES;
    grid_barrier(1 * NBLK_SCAN);

    // phase 1: degree histogram (int4)
    for (int i4 = gid; i4 < N_EDGES / 4; i4 += NT) {
        int4 d = reinterpret_cast<const int4*>(dst)[i4];
        atomicAdd(&g_cnt[d.x], 1);
        atomicAdd(&g_cnt[d.y], 1);
        atomicAdd(&g_cnt[d.z], 1);
        atomicAdd(&g_cnt[d.w], 1);
    }
    grid_barrier(2 * NBLK_SCAN);

    // phase 2: per-block inclusive scan
    int v = (gid < N_NODES) ? g_cnt[gid] : 0;
    s[tid] = v;
    __syncthreads();
    for (int o = 1; o < SCAN_BLK; o <<= 1) {
        int t = (tid >= o) ? s[tid - o] : 0;
        __syncthreads();
        s[tid] += t;
        __syncthreads();
    }
    if (tid == SCAN_BLK - 1) g_bsum[b] = s[tid];
    grid_barrier(3 * NBLK_SCAN);

    // phase 3: global offsets + norms
    if (tid == 0) {
        int run = 0;
        for (int q = 0; q < b; q++) run += g_bsum[q];
        sprefix = run;
    }
    __syncthreads();
    if (gid < N_NODES) {
        int off = sprefix + s[tid] - v;   // exclusive
        g_off[gid] = off;
        g_fill[gid] = off;                // working cursor
        g_dis[gid] = rsqrtf((float)v + 1.0f);
    }
    grid_barrier(4 * NBLK_SCAN);

    // phase 4: CSR fill (src only, pre-shifted)
    for (int e = gid; e < N_EDGES; e += NT) {
        int ss = src[e], dd = dst[e];
        int pos = atomicAdd(&g_fill[dd], 1);
        g_csr[pos] = ss << 5;
    }
}

// ---------------- y0 = dis * (X @ W1), tiled GEMM; also resets barrier counter ----------------
__global__ void k_gemm1(const float* __restrict__ X, const float* __restrict__ W) {
    __shared__ float Xs[GM_NODES * INDIM];   // 16 KB
    __shared__ float Ws[INDIM * DIMC];       // 16 KB
    int tid = threadIdx.x;
    int nbase = blockIdx.x * GM_NODES;
    if (blockIdx.x == 0 && tid == 0) g_syncc = 0;   // reset for next replay

    const float4* Wg = reinterpret_cast<const float4*>(W);
    float4* Ws4 = reinterpret_cast<float4*>(Ws);
    for (int i = tid; i < INDIM * DIMC / 4; i += 256) Ws4[i] = Wg[i];
    const float4* Xg = reinterpret_cast<const float4*>(X + (size_t)nbase * INDIM);
    float4* Xs4 = reinterpret_cast<float4*>(Xs);
    for (int i = tid; i < GM_NODES * INDIM / 4; i += 256) Xs4[i] = Xg[i];
    __syncthreads();

    int dim = tid & 31, nq = tid >> 5;
    const float* xr0 = Xs + (nq * 4 + 0) * INDIM;
    const float* xr1 = Xs + (nq * 4 + 1) * INDIM;
    const float* xr2 = Xs + (nq * 4 + 2) * INDIM;
    const float* xr3 = Xs + (nq * 4 + 3) * INDIM;
    float a0 = 0.f, a1 = 0.f, a2 = 0.f, a3 = 0.f;
#pragma unroll 4
    for (int kb = 0; kb < INDIM; kb += 4) {
        float w0 = Ws[(kb + 0) * DIMC + dim];
        float w1 = Ws[(kb + 1) * DIMC + dim];
        float w2 = Ws[(kb + 2) * DIMC + dim];
        float w3 = Ws[(kb + 3) * DIMC + dim];
        float4 v0 = *reinterpret_cast<const float4*>(xr0 + kb);
        float4 v1 = *reinterpret_cast<const float4*>(xr1 + kb);
        float4 v2 = *reinterpret_cast<const float4*>(xr2 + kb);
        float4 v3 = *reinterpret_cast<const float4*>(xr3 + kb);
        a0 = fmaf(v0.x, w0, a0); a0 = fmaf(v0.y, w1, a0);
        a0 = fmaf(v0.z, w2, a0); a0 = fmaf(v0.w, w3, a0);
        a1 = fmaf(v1.x, w0, a1); a1 = fmaf(v1.y, w1, a1);
        a1 = fmaf(v1.z, w2, a1); a1 = fmaf(v1.w, w3, a1);
        a2 = fmaf(v2.x, w0, a2); a2 = fmaf(v2.y, w1, a2);
        a2 = fmaf(v2.z, w2, a2); a2 = fmaf(v2.w, w3, a2);
        a3 = fmaf(v3.x, w0, a3); a3 = fmaf(v3.y, w1, a3);
        a3 = fmaf(v3.z, w2, a3); a3 = fmaf(v3.w, w3, a3);
    }
    int nb = nbase + nq * 4;
    g_y0[(nb + 0) * DIMC + dim] = a0 * g_dis[nb + 0];
    g_y0[(nb + 1) * DIMC + dim] = a1 * g_dis[nb + 1];
    g_y0[(nb + 2) * DIMC + dim] = a2 * g_dis[nb + 2];
    g_y0[(nb + 3) * DIMC + dim] = a3 * g_dis[nb + 3];
}

// ---------------- CSR gather on y + fused transform ----------------
// z = dis[d] * (sum_{s in N(d)} y[s] + y[d])
// layer 1: x1 = tanh(z+b), y1 = dis*x1
// layer 2: x2 = tanh(z@W+b), y2 = dis*x2
// layer 3: x3 = tanh(z@W+b), score = tanh(z.W4+b4)
__global__ void __launch_bounds__(256) k_gather(int layer, const float* __restrict__ W,
                         const float* __restrict__ b,
                         const float* __restrict__ W4, const float* __restrict__ b4) {
    __shared__ float Ws[DIMC * DIMC];
    int tid = threadIdx.x;
    if (layer >= 2) {
        for (int i = tid; i < DIMC * DIMC; i += 256) Ws[i] = W[i];
        __syncthreads();
    }
    const float* __restrict__ Y = (layer == 1) ? g_y0 : (layer == 2 ? g_y1 : g_y2);
    int node = blockIdx.x * 8 + (tid >> 5);
    if (node >= N_NODES) return;
    int lane = tid & 31;
    int grp = lane >> 3, sub = lane & 7;
    int beg = g_off[node], end = g_off[node + 1];

    float4 acc = make_float4(0.f, 0.f, 0.f, 0.f);
    for (int base = beg; base < end; base += 16) {
        int e0 = base + grp, e1 = e0 + 4, e2 = e0 + 8, e3 = e0 + 12;
        int s0 = 0, s1 = 0, s2 = 0, s3 = 0;
        float m0 = 0.f, m1 = 0.f, m2 = 0.f, m3 = 0.f;
        if (e0 < end) { s0 = g_csr[e0]; m0 = 1.f; }
        if (e1 < end) { s1 = g_csr[e1]; m1 = 1.f; }
        if (e2 < end) { s2 = g_csr[e2]; m2 = 1.f; }
        if (e3 < end) { s3 = g_csr[e3]; m3 = 1.f; }
        const float4 v0 = *reinterpret_cast<const float4*>(Y + s0 + sub * 4);
        const float4 v1 = *reinterpret_cast<const float4*>(Y + s1 + sub * 4);
        const float4 v2 = *reinterpret_cast<const float4*>(Y + s2 + sub * 4);
        const float4 v3 = *reinterpret_cast<const float4*>(Y + s3 + sub * 4);
        acc.x = fmaf(m0, v0.x, fmaf(m1, v1.x, fmaf(m2, v2.x, fmaf(m3, v3.x, acc.x))));
        acc.y = fmaf(m0, v0.y, fmaf(m1, v1.y, fmaf(m2, v2.y, fmaf(m3, v3.y, acc.y))));
        acc.z = fmaf(m0, v0.z, fmaf(m1, v1.z, fmaf(m2, v2.z, fmaf(m3, v3.z, acc.z))));
        acc.w = fmaf(m0, v0.w, fmaf(m1, v1.w, fmaf(m2, v2.w, fmaf(m3, v3.w, acc.w))));
    }
#pragma unroll
    for (int off = 8; off <= 16; off <<= 1) {
        acc.x += __shfl_xor_sync(0xffffffffu, acc.x, off);
        acc.y += __shfl_xor_sync(0xffffffffu, acc.y, off);
        acc.z += __shfl_xor_sync(0xffffffffu, acc.z, off);
        acc.w += __shfl_xor_sync(0xffffffffu, acc.w, off);
    }
    float dis = g_dis[node];
    const float4 yself = *reinterpret_cast<const float4*>(Y + node * DIMC + sub * 4);
    acc.x = (acc.x + yself.x) * dis;
    acc.y = (acc.y + yself.y) * dis;
    acc.z = (acc.z + yself.z) * dis;
    acc.w = (acc.w + yself.w) * dis;
    // acc now holds z for dims sub*4..sub*4+3 (replicated over grp)

    if (layer == 1) {
        if (grp == 0) {
            float4 o;
            o.x = tanhf(acc.x + b[sub * 4 + 0]);
            o.y = tanhf(acc.y + b[sub * 4 + 1]);
            o.z = tanhf(acc.z + b[sub * 4 + 2]);
            o.w = tanhf(acc.w + b[sub * 4 + 3]);
            *reinterpret_cast<float4*>(&g_x1[node * DIMC + sub * 4]) = o;
            float4 y;
            y.x = o.x * dis; y.y = o.y * dis; y.z = o.z * dis; y.w = o.w * dis;
            *reinterpret_cast<float4*>(&g_y1[node * DIMC + sub * 4]) = y;
        }
        return;
    }

    float outacc = 0.0f;
#pragma unroll
    for (int jb = 0; jb < 8; jb++) {
        float z0 = __shfl_sync(0xffffffffu, acc.x, jb);
        float z1 = __shfl_sync(0xffffffffu, acc.y, jb);
        float z2 = __shfl_sync(0xffffffffu, acc.z, jb);
        float z3 = __shfl_sync(0xffffffffu, acc.w, jb);
        outacc = fmaf(z0, Ws[(jb * 4 + 0) * DIMC + lane], outacc);
        outacc = fmaf(z1, Ws[(jb * 4 + 1) * DIMC + lane], outacc);
        outacc = fmaf(z2, Ws[(jb * 4 + 2) * DIMC + lane], outacc);
        outacc = fmaf(z3, Ws[(jb * 4 + 3) * DIMC + lane], outacc);
    }
    float o = tanhf(outacc + b[lane]);
    if (layer == 2) {
        g_x2[node * DIMC + lane] = o;
        g_y2[node * DIMC + lane] = o * dis;
    } else {
        g_x3[node * DIMC + lane] = o;
        float t = acc.x * W4[sub * 4 + 0] + acc.y * W4[sub * 4 + 1]
                + acc.z * W4[sub * 4 + 2] + acc.w * W4[sub * 4 + 3];
        t += __shfl_xor_sync(0xffffffffu, t, 1);
        t += __shfl_xor_sync(0xffffffffu, t, 2);
        t += __shfl_xor_sync(0xffffffffu, t, 4);
        if (lane == 0) g_score[node] = tanhf(t + b4[0]);
    }
}

// ---------------- fused tail: sortpool -> conv1+pool -> conv2 (one block/graph) ----------------
__global__ void __launch_bounds__(256) k_tail(const float* __restrict__ cw1,
                                              const float* __restrict__ cb1,
                                              const float* __restrict__ cw2,
                                              const float* __restrict__ cb2) {
    __shared__ float s[512];
    __shared__ int   si[512];
    __shared__ float xs[KTOP * TOTALC];   // 38.8 KB; reused as ps (128*50) for conv2
    int g = blockIdx.x, tid = threadIdx.x;

    // --- sort (bitonic 512, desc by score, tie: idx asc) ---
    for (int i = tid; i < 512; i += 256) {
        if (i < NPER) { s[i] = g_score[g * NPER + i]; si[i] = i; }
        else          { s[i] = __int_as_float(0xff800000); si[i] = 0x7FFFFFFF; }
    }
    __syncthreads();
    for (int k = 2; k <= 512; k <<= 1) {
        for (int j = k >> 1; j > 0; j >>= 1) {
            for (int i = tid; i < 512; i += 256) {
                int ixj = i ^ j;
                if (ixj > i) {
                    float a = s[i], bb = s[ixj];
                    int ia = si[i], ib = si[ixj];
                    bool before = (a > bb) || (a == bb && ia < ib);
                    bool dirDesc = ((i & k) == 0);
                    if (dirDesc ? !before : before) {
                        s[i] = bb; s[ixj] = a; si[i] = ib; si[ixj] = ia;
                    }
                }
            }
            __syncthreads();
        }
    }

    // --- build xs[100][97] from top-k ---
    for (int i = tid; i < KTOP * TOTALC; i += 256) {
        int kslot = i / TOTALC, t = i - kslot * TOTALC;
        int n = g * NPER + si[kslot];
        float v;
        if (t < 32)      v = g_x1[n * DIMC + t];
        else if (t < 64) v = g_x2[n * DIMC + t - 32];
        else if (t < 96) v = g_x3[n * DIMC + t - 64];
        else             v = g_score[n];
        xs[i] = v;
    }
    __syncthreads();

    // --- conv1 + relu + maxpool(2,2): results staged in registers ---
    float pr[28];
    int nit = 0;
    for (int item = tid; item < 32 * 50; item += 256, nit++) {
        int cb = item / 50, j = item - cb * 50;
        const float* r0 = xs + (2 * j) * TOTALC;
        const float* r1 = r0 + TOTALC;
        float a[8];
#pragma unroll
        for (int q = 0; q < 4; q++) { float bb = cb1[cb + q * 32]; a[q] = bb; a[4 + q] = bb; }
#pragma unroll 2
        for (int t = 0; t < TOTALC; t++) {
            float v0 = r0[t], v1 = r1[t];
#pragma unroll
            for (int q = 0; q < 4; q++) {
                float wv = cw1[(cb + q * 32) * TOTALC + t];
                a[q]     = fmaf(v0, wv, a[q]);
                a[4 + q] = fmaf(v1, wv, a[4 + q]);
            }
        }
#pragma unroll
        for (int q = 0; q < 4; q++)
            pr[nit * 4 + q] = fmaxf(fmaxf(a[q], a[4 + q]), 0.0f);
    }
    __syncthreads();
    // store pooled map into reused xs region
    float* ps = xs;
    nit = 0;
    for (int item = tid; item < 32 * 50; item += 256, nit++) {
        int cb = item / 50, j = item - cb * 50;
#pragma unroll
        for (int q = 0; q < 4; q++)
            ps[(cb + q * 32) * 50 + j] = pr[nit * 4 + q];
    }
    __syncthreads();

    // --- conv2 (128->64, k=5) + relu -> g_c2f ---
    for (int item = tid; item < 16 * 46; item += 256) {
        int ob = item / 46, j = item - ob * 46;
        float a0 = cb2[ob], a1 = cb2[ob + 16], a2 = cb2[ob + 32], a3 = cb2[ob + 48];
        const float* w0 = cw2 + (ob)      * 640;
        const float* w1 = cw2 + (ob + 16) * 640;
        const float* w2 = cw2 + (ob + 32) * 640;
        const float* w3 = cw2 + (ob + 48) * 640;
#pragma unroll 2
        for (int i = 0; i < 128; i++) {
            const float* pp = ps + i * 50 + j;
            float p0 = pp[0], p1 = pp[1], p2 = pp[2], p3 = pp[3], p4 = pp[4];
            const float* q0 = w0 + i * 5;
            const float* q1 = w1 + i * 5;
            const float* q2 = w2 + i * 5;
            const float* q3 = w3 + i * 5;
            a0 = fmaf(p0, q0[0], a0); a0 = fmaf(p1, q0[1], a0); a0 = fmaf(p2, q0[2], a0);
            a0 = fmaf(p3, q0[3], a0); a0 = fmaf(p4, q0[4], a0);
            a1 = fmaf(p0, q1[0], a1); a1 = fmaf(p1, q1[1], a1); a1 = fmaf(p2, q1[2], a1);
            a1 = fmaf(p3, q1[3], a1); a1 = fmaf(p4, q1[4], a1);
            a2 = fmaf(p0, q2[0], a2); a2 = fmaf(p1, q2[1], a2); a2 = fmaf(p2, q2[2], a2);
            a2 = fmaf(p3, q2[3], a2); a2 = fmaf(p4, q2[4], a2);
            a3 = fmaf(p0, q3[0], a3); a3 = fmaf(p1, q3[1], a3); a3 = fmaf(p2, q3[2], a3);
            a3 = fmaf(p3, q3[3], a3); a3 = fmaf(p4, q3[4], a3);
        }
        g_c2f[g * 2944 + (ob)      * 46 + j] = fmaxf(a0, 0.0f);
        g_c2f[g * 2944 + (ob + 16) * 46 + j] = fmaxf(a1, 0.0f);
        g_c2f[g * 2944 + (ob + 32) * 46 + j] = fmaxf(a2, 0.0f);
        g_c2f[g * 2944 + (ob + 48) * 46 + j] = fmaxf(a3, 0.0f);
    }
}

// ---------------- fc1 + relu + fc3 + log_softmax (4 graphs per block) ----------------
__global__ void __launch_bounds__(256) k_fc(const float* __restrict__ fw1,
                                            const float* __restrict__ fb1,
                                            const float* __restrict__ fw3,
                                            const float* __restrict__ fb3,
                                            float* __restrict__ out) {
    __shared__ float cs[4 * 2944];        // 47.1 KB; first 512 reused for hfc
    __shared__ float part[256];
    int gb = blockIdx.x, tid = threadIdx.x;
    int g0 = gb * 4;
    for (int i = tid; i < 4 * 2944; i += 256) {
        int g = g0 + i / 2944;
        cs[i] = (g < NGRAPH) ? g_c2f[g * 2944 + (i % 2944)] : 0.0f;
    }
    __syncthreads();
    int half = tid >> 7;
    int o    = tid & 127;
    int dbeg = half * 368;
    const float4* wr = reinterpret_cast<const float4*>(fw1 + (size_t)o * 2944) + dbeg;
    const float4* c0 = reinterpret_cast<const float4*>(cs) + dbeg;
    const float4* c1 = reinterpret_cast<const float4*>(cs + 2944) + dbeg;
    const float4* c2 = reinterpret_cast<const float4*>(cs + 2 * 2944) + dbeg;
    const float4* c3 = reinterpret_cast<const float4*>(cs + 3 * 2944) + dbeg;
    float a0 = 0, a1 = 0, a2 = 0, a3 = 0;
    for (int d = 0; d < 368; d++) {
        float4 w = wr[d];
        float4 v;
        v = c0[d]; a0 += w.x * v.x + w.y * v.y + w.z * v.z + w.w * v.w;
        v = c1[d]; a1 += w.x * v.x + w.y * v.y + w.z * v.z + w.w * v.w;
        v = c2[d]; a2 += w.x * v.x + w.y * v.y + w.z * v.z + w.w * v.w;
        v = c3[d]; a3 += w.x * v.x + w.y * v.y + w.z * v.z + w.w * v.w;
    }
    if (half == 1) { part[o] = a0; part[o + 128] = a1; }
    __syncthreads();
    if (half == 0) { a0 += part[o]; a1 += part[o + 128]; }
    __syncthreads();
    if (half == 1) { part[o] = a2; part[o + 128] = a3; }
    __syncthreads();
    if (half == 0) {
        a2 += part[o]; a3 += part[o + 128];
        float bb = fb1[o];
        cs[0 * 128 + o] = fmaxf(a0 + bb, 0.0f);
        cs[1 * 128 + o] = fmaxf(a1 + bb, 0.0f);
        cs[2 * 128 + o] = fmaxf(a2 + bb, 0.0f);
        cs[3 * 128 + o] = fmaxf(a3 + bb, 0.0f);
    }
    __syncthreads();
    // fc3 + log_softmax: warp q handles graph g0+q
    int wid = tid >> 5, lane = tid & 31;
    if (wid < 4 && g0 + wid < NGRAPH) {
        float l0 = 0.f, l1 = 0.f;
#pragma unroll
        for (int k = 0; k < 4; k++) {
            int d = lane + 32 * k;
            float h = cs[wid * 128 + d];
            l0 = fmaf(h, fw3[d], l0);
            l1 = fmaf(h, fw3[128 + d], l1);
        }
#pragma unroll
        for (int off = 16; off; off >>= 1) {
            l0 += __shfl_xor_sync(0xffffffffu, l0, off);
            l1 += __shfl_xor_sync(0xffffffffu, l1, off);
        }
        if (lane == 0) {
            l0 += fb3[0]; l1 += fb3[1];
            float m = fmaxf(l0, l1);
            float lse = m + logf(expf(l0 - m) + expf(l1 - m));
            out[(g0 + wid) * 2 + 0] = l0 - lse;
            out[(g0 + wid) * 2 + 1] = l1 - lse;
        }
    }
}

// ---------------- launch ----------------
extern "C" void kernel_launch(void* const* d_in, const int* in_sizes, int n_in,
                              void* d_out, int out_size) {
    const float* x   = (const float*)d_in[0];
    const int*   ei  = (const int*)d_in[1];
    const int*   src = ei;
    const int*   dst = ei + N_EDGES;
    const float* W1 = (const float*)d_in[3];  const float* b1 = (const float*)d_in[4];
    const float* W2 = (const float*)d_in[5];  const float* b2 = (const float*)d_in[6];
    const float* W3 = (const float*)d_in[7];  const float* b3 = (const float*)d_in[8];
    const float* W4 = (const float*)d_in[9];  const float* b4 = (const float*)d_in[10];
    const float* cw1 = (const float*)d_in[11]; const float* cb1 = (const float*)d_in[12];
    const float* cw2 = (const float*)d_in[13]; const float* cb2 = (const float*)d_in[14];
    const float* fw1 = (const float*)d_in[15]; const float* fb1 = (const float*)d_in[16];
    const float* fw3 = (const float*)d_in[17]; const float* fb3 = (const float*)d_in[18];
    float* out = (float*)d_out;

    const int TB = 256;
    const int gG8 = (N_NODES + 7) / 8;           // 12500

    k_scanfill<<<NBLK_SCAN, SCAN_BLK>>>(src, dst);            // 0
    k_gemm1<<<N_NODES / GM_NODES, TB>>>(x, W1);               // 1 (resets barrier ctr)
    k_gather<<<gG8, TB>>>(1, nullptr, b1, nullptr, nullptr);  // 2
    k_gather<<<gG8, TB>>>(2, W2, b2, nullptr, nullptr);       // 3 <- profiled
    k_gather<<<gG8, TB>>>(3, W3, b3, W4, b4);                 // 4
    k_tail<<<NGRAPH, TB>>>(cw1, cb1, cw2, cb2);               // 5
    k_fc<<<(NGRAPH + 3) / 4, TB>>>(fw1, fb1, fw3, fb3, out);  // 6
}